// round 1
// baseline (speedup 1.0000x reference)
#include <cuda_runtime.h>
#include <math.h>

#define BB 4
#define CC 64
#define MM 8
#define HH 224
#define WW 224
#define NN (HH*WW)      // 50176
#define BN (BB*NN)      // 200704
#define TN 128          // KV n-chunk

// Scratch (static device globals — allocation-free per harness rules)
__device__ float g_h[BB*CC*NN];
__device__ float g_s[BB*CC*NN];
__device__ float g_V[BB*CC*NN];
__device__ float g_Q[BB*MM*NN];
__device__ float g_K[BB*MM*NN];
__device__ float g_KV[BB*MM*CC];
__device__ float g_Ksum[BB*MM];

__device__ __forceinline__ float relu6f(float x){ return fminf(fmaxf(x,0.f),6.f); }
__device__ __forceinline__ float softplusf(float x){
    return fmaxf(x,0.f) + log1pf(expf(-fabsf(x)));
}

__global__ void k_zero(){
    int i = blockIdx.x*blockDim.x + threadIdx.x;
    if (i < BB*MM*CC) g_KV[i]   = 0.f;
    if (i < BB*MM)    g_Ksum[i] = 0.f;
}

// ---------------------------------------------------------------------------
// K1: per pixel — Q,K (softplus), Ksum (warp-reduced atomics),
//     h = relu6(bn(fc1(x))), Vpart = v_conv(x)+v_b
// ---------------------------------------------------------------------------
__global__ __launch_bounds__(256) void k_front(
    const float* __restrict__ x,
    const float* __restrict__ q_w, const float* __restrict__ q_b,
    const float* __restrict__ k_w, const float* __restrict__ k_b,
    const float* __restrict__ v_w, const float* __restrict__ v_b,
    const float* __restrict__ fc1_w, const float* __restrict__ fc1_bn)
{
    __shared__ __align__(16) float s_wq[MM*CC];
    __shared__ __align__(16) float s_wk[MM*CC];
    __shared__ __align__(16) float s_wv[CC*CC];
    __shared__ __align__(16) float s_wf[CC*CC];
    __shared__ float s_qb[MM], s_kb[MM], s_vb[CC], s_finv[CC], s_fbeta[CC];

    int tid = threadIdx.x;
    for (int i=tid;i<MM*CC;i+=256){ s_wq[i]=q_w[i]; s_wk[i]=k_w[i]; }
    for (int i=tid;i<CC*CC;i+=256){ s_wv[i]=v_w[i]; s_wf[i]=fc1_w[i]; }
    if (tid<MM){ s_qb[tid]=q_b[tid]; s_kb[tid]=k_b[tid]; }
    if (tid<CC){
        s_vb[tid]=v_b[tid];
        float sc=fc1_bn[0*CC+tid], bi=fc1_bn[1*CC+tid];
        float mn=fc1_bn[2*CC+tid], vr=fc1_bn[3*CC+tid];
        float inv = sc*rsqrtf(vr+1e-5f);
        s_finv[tid]=inv; s_fbeta[tid]=bi-mn*inv;
    }
    __syncthreads();

    int p = blockIdx.x*256 + tid;
    int b = p / NN, n = p % NN;
    const float* xb = x + b*CC*NN + n;

    float xv[CC];
    #pragma unroll
    for (int c=0;c<CC;c++) xv[c] = xb[c*NN];

    // ---- Q / K ----
    float kreg[MM];
    const float4* wq4 = (const float4*)s_wq;
    const float4* wk4 = (const float4*)s_wk;
    #pragma unroll
    for (int m=0;m<MM;m++){
        float aq=0.f, ak=0.f;
        #pragma unroll
        for (int c4=0;c4<16;c4++){
            float4 a = wq4[m*16+c4];
            float4 bq = wk4[m*16+c4];
            aq += a.x*xv[4*c4+0] + a.y*xv[4*c4+1] + a.z*xv[4*c4+2] + a.w*xv[4*c4+3];
            ak += bq.x*xv[4*c4+0] + bq.y*xv[4*c4+1] + bq.z*xv[4*c4+2] + bq.w*xv[4*c4+3];
        }
        float qv = softplusf(aq + s_qb[m]);
        float kv = softplusf(ak + s_kb[m]);
        g_Q[b*MM*NN + m*NN + n] = qv;
        g_K[b*MM*NN + m*NN + n] = kv;
        kreg[m] = kv;
    }

    // ---- Ksum (warp-level reduction; N % 32 == 0 so b is warp-uniform) ----
    #pragma unroll
    for (int m=0;m<MM;m++){
        float v = kreg[m];
        #pragma unroll
        for (int off=16;off;off>>=1) v += __shfl_down_sync(0xffffffffu, v, off);
        if ((tid&31)==0) atomicAdd(&g_Ksum[b*MM+m], v);
    }

    // ---- h = relu6(bn(fc1(x))),  Vpart ----
    const float4* wv4 = (const float4*)s_wv;
    const float4* wf4 = (const float4*)s_wf;
    #pragma unroll 4
    for (int o=0;o<CC;o++){
        float av=0.f, af=0.f;
        #pragma unroll
        for (int c4=0;c4<16;c4++){
            float4 a = wv4[o*16+c4];
            float4 f = wf4[o*16+c4];
            av += a.x*xv[4*c4+0] + a.y*xv[4*c4+1] + a.z*xv[4*c4+2] + a.w*xv[4*c4+3];
            af += f.x*xv[4*c4+0] + f.y*xv[4*c4+1] + f.z*xv[4*c4+2] + f.w*xv[4*c4+3];
        }
        g_V[b*CC*NN + o*NN + n] = av + s_vb[o];
        g_h[b*CC*NN + o*NN + n] = relu6f(af*s_finv[o] + s_fbeta[o]);
    }
}

// ---------------------------------------------------------------------------
// K2: depthwise 5x5 + 3x3 (both BN+ReLU6), summed -> g_s
// ---------------------------------------------------------------------------
__global__ __launch_bounds__(256) void k_dw(
    const float* __restrict__ w5, const float* __restrict__ bn5,
    const float* __restrict__ w3, const float* __restrict__ bn3)
{
    int bc = blockIdx.z;           // b*CC + c
    int c  = bc & (CC-1);
    int y0 = blockIdx.y*8, x0 = blockIdx.x*32;

    __shared__ float t[12][36];
    __shared__ float s_w5[25], s_w3[9], s_c[4];

    int tid = threadIdx.y*32 + threadIdx.x;
    const float* plane = g_h + bc*NN;

    for (int i=tid;i<12*36;i+=256){
        int ly=i/36, lx=i%36;
        int gy=y0+ly-2, gx=x0+lx-2;
        float v = 0.f;
        if (gy>=0 && gy<HH && gx>=0 && gx<WW) v = plane[gy*WW+gx];
        t[ly][lx] = v;
    }
    if (tid<25) s_w5[tid] = w5[c*25+tid];
    if (tid<9)  s_w3[tid] = w3[c*9+tid];
    if (tid==0){
        float inv = bn5[0*CC+c]*rsqrtf(bn5[3*CC+c]+1e-5f);
        s_c[0]=inv; s_c[1]=bn5[1*CC+c]-bn5[2*CC+c]*inv;
    }
    if (tid==32){
        float inv = bn3[0*CC+c]*rsqrtf(bn3[3*CC+c]+1e-5f);
        s_c[2]=inv; s_c[3]=bn3[1*CC+c]-bn3[2*CC+c]*inv;
    }
    __syncthreads();

    int ty=threadIdx.y, tx=threadIdx.x;
    float a5=0.f;
    #pragma unroll
    for (int i=0;i<5;i++)
        #pragma unroll
        for (int j=0;j<5;j++)
            a5 += s_w5[i*5+j]*t[ty+i][tx+j];
    float a3=0.f;
    #pragma unroll
    for (int i=0;i<3;i++)
        #pragma unroll
        for (int j=0;j<3;j++)
            a3 += s_w3[i*3+j]*t[ty+1+i][tx+1+j];

    float r = relu6f(a5*s_c[0]+s_c[1]) + relu6f(a3*s_c[2]+s_c[3]);
    g_s[bc*NN + (y0+ty)*WW + (x0+tx)] = r;
}

// ---------------------------------------------------------------------------
// K3: x_channel = relu6(bn(fc2(s))); V += x_channel  (in place)
// ---------------------------------------------------------------------------
__global__ __launch_bounds__(256) void k_fc2(
    const float* __restrict__ fc2_w, const float* __restrict__ fc2_bn)
{
    __shared__ __align__(16) float s_w[CC*CC];
    __shared__ float s_inv[CC], s_beta[CC];
    int tid = threadIdx.x;
    for (int i=tid;i<CC*CC;i+=256) s_w[i] = fc2_w[i];
    if (tid<CC){
        float sc=fc2_bn[0*CC+tid], bi=fc2_bn[1*CC+tid];
        float mn=fc2_bn[2*CC+tid], vr=fc2_bn[3*CC+tid];
        float inv = sc*rsqrtf(vr+1e-5f);
        s_inv[tid]=inv; s_beta[tid]=bi-mn*inv;
    }
    __syncthreads();

    int p = blockIdx.x*256 + tid;
    int b = p/NN, n = p%NN;
    const float* sp = g_s + b*CC*NN + n;
    float* vp = g_V + b*CC*NN + n;

    float sv[CC];
    #pragma unroll
    for (int c=0;c<CC;c++) sv[c] = sp[c*NN];

    const float4* w4 = (const float4*)s_w;
    #pragma unroll 4
    for (int o=0;o<CC;o++){
        float a=0.f;
        #pragma unroll
        for (int c4=0;c4<16;c4++){
            float4 w = w4[o*16+c4];
            a += w.x*sv[4*c4+0] + w.y*sv[4*c4+1] + w.z*sv[4*c4+2] + w.w*sv[4*c4+3];
        }
        vp[o*NN] += relu6f(a*s_inv[o] + s_beta[o]);
    }
}

// ---------------------------------------------------------------------------
// K4: KV[b,m,c] = sum_n K[b,m,n]*V[b,c,n]  (tiled smem, global atomics)
// ---------------------------------------------------------------------------
__global__ __launch_bounds__(256) void k_kv()
{
    int blk = blockIdx.x;
    int b  = blk / (NN/TN);
    int n0 = (blk % (NN/TN)) * TN;

    __shared__ float Vs[CC][TN+1];   // +1 pad: conflict-free column reads
    __shared__ float Ks[MM][TN];

    int tid = threadIdx.x;
    const float* Vb = g_V + b*CC*NN + n0;
    for (int i=tid;i<CC*TN;i+=256){ int c=i/TN, n=i%TN; Vs[c][n]=Vb[c*NN+n]; }
    const float* Kb = g_K + b*MM*NN + n0;
    for (int i=tid;i<MM*TN;i+=256){ int m=i/TN, n=i%TN; Ks[m][n]=Kb[m*NN+n]; }
    __syncthreads();

    int m = tid>>6;       // 0..3
    int c = tid & 63;     // 0..63
    float a0=0.f, a1=0.f;
    #pragma unroll 8
    for (int n=0;n<TN;n++){
        float vv = Vs[c][n];
        a0 += Ks[m  ][n]*vv;
        a1 += Ks[m+4][n]*vv;
    }
    atomicAdd(&g_KV[b*MM*CC + m*CC     + c], a0);
    atomicAdd(&g_KV[b*MM*CC + (m+4)*CC + c], a1);
}

// ---------------------------------------------------------------------------
// K5: out[b,c,n] = x + gamma * (sum_m Q[m,n]*KV[m,c]) / (sum_m Q[m,n]*(Ksum[m]+eps))
// ---------------------------------------------------------------------------
__global__ __launch_bounds__(256) void k_out(
    const float* __restrict__ x, const float* __restrict__ gamma,
    float* __restrict__ out)
{
    __shared__ __align__(16) float s_kv[MM*CC];
    __shared__ float s_ks[MM];
    int tid = threadIdx.x;
    int p = blockIdx.x*256 + tid;
    int b = p/NN, n = p%NN;     // NN % 256 == 0 -> b is block-uniform

    for (int i=tid;i<MM*CC;i+=256) s_kv[i] = g_KV[b*MM*CC + i];
    if (tid<MM) s_ks[tid] = g_Ksum[b*MM+tid] + 1e-6f;
    __syncthreads();

    float q[MM];
    #pragma unroll
    for (int m=0;m<MM;m++) q[m] = g_Q[b*MM*NN + m*NN + n];

    float den=0.f;
    #pragma unroll
    for (int m=0;m<MM;m++) den += q[m]*s_ks[m];
    float gs = gamma[0] / den;

    const float* xb = x + b*CC*NN + n;
    float* ob = out + b*CC*NN + n;

    const float4* kv4 = (const float4*)s_kv;
    #pragma unroll 4
    for (int c4=0;c4<16;c4++){
        float ax=0.f, ay=0.f, az=0.f, aw=0.f;
        #pragma unroll
        for (int m=0;m<MM;m++){
            float4 w = kv4[m*16+c4];
            ax += q[m]*w.x; ay += q[m]*w.y; az += q[m]*w.z; aw += q[m]*w.w;
        }
        int c = 4*c4;
        ob[(c+0)*NN] = xb[(c+0)*NN] + gs*ax;
        ob[(c+1)*NN] = xb[(c+1)*NN] + gs*ay;
        ob[(c+2)*NN] = xb[(c+2)*NN] + gs*az;
        ob[(c+3)*NN] = xb[(c+3)*NN] + gs*aw;
    }
}

// ---------------------------------------------------------------------------
extern "C" void kernel_launch(void* const* d_in, const int* in_sizes, int n_in,
                              void* d_out, int out_size)
{
    const float* x      = (const float*)d_in[0];
    const float* gamma  = (const float*)d_in[1];
    const float* q_w    = (const float*)d_in[2];
    const float* q_b    = (const float*)d_in[3];
    const float* k_w    = (const float*)d_in[4];
    const float* k_b    = (const float*)d_in[5];
    const float* v_w    = (const float*)d_in[6];
    const float* v_b    = (const float*)d_in[7];
    const float* fc1_w  = (const float*)d_in[8];
    const float* fc1_bn = (const float*)d_in[9];
    const float* c1_w   = (const float*)d_in[10];
    const float* c1_bn  = (const float*)d_in[11];
    const float* c2_w   = (const float*)d_in[12];
    const float* c2_bn  = (const float*)d_in[13];
    const float* fc2_w  = (const float*)d_in[14];
    const float* fc2_bn = (const float*)d_in[15];
    float* out = (float*)d_out;

    k_zero<<<8,256>>>();
    k_front<<<BN/256,256>>>(x,q_w,q_b,k_w,k_b,v_w,v_b,fc1_w,fc1_bn);
    k_dw<<<dim3(WW/32,HH/8,BB*CC),dim3(32,8)>>>(c1_w,c1_bn,c2_w,c2_bn);
    k_fc2<<<BN/256,256>>>(fc2_w,fc2_bn);
    k_kv<<<BB*(NN/TN),256>>>();
    k_out<<<BN/256,256>>>(x,gamma,out);
}

// round 2
// speedup vs baseline: 1.0943x; 1.0943x over previous
#include <cuda_runtime.h>
#include <math.h>

#define BB 4
#define CC 64
#define MM 8
#define HH 224
#define WW 224
#define NN (HH*WW)      // 50176
#define BN (BB*NN)      // 200704
#define TN 128          // KV n-chunk
#define TP 128          // GEMM pixel tile

// Scratch (static device globals — allocation-free per harness rules)
__device__ float g_h[BB*CC*NN];
__device__ float g_s[BB*CC*NN];
__device__ float g_V[BB*CC*NN];
__device__ float g_Q[BB*MM*NN];
__device__ float g_K[BB*MM*NN];
__device__ float g_KV[BB*MM*CC];
__device__ float g_Ksum[BB*MM];

__device__ __forceinline__ float relu6f(float x){ return fminf(fmaxf(x,0.f),6.f); }
__device__ __forceinline__ float softplusf(float x){
    return fmaxf(x,0.f) + log1pf(expf(-fabsf(x)));
}

__global__ void k_zero(){
    int i = blockIdx.x*blockDim.x + threadIdx.x;
    if (i < BB*MM*CC) g_KV[i]   = 0.f;
    if (i < BB*MM)    g_Ksum[i] = 0.f;
}

#define STEP(i, ws) { acc[i].x = fmaf(ws, xv.x, acc[i].x); \
                      acc[i].y = fmaf(ws, xv.y, acc[i].y); \
                      acc[i].z = fmaf(ws, xv.z, acc[i].z); \
                      acc[i].w = fmaf(ws, xv.w, acc[i].w); }

// ---------------------------------------------------------------------------
// K1 front: tiled GEMM, 144 outputs = [v(64) | fc1(64) | q(8) | k(8)], K=64.
// Block: 288 threads (9 warps). ty = warp = output-group of 16; tx = pixel/4.
// Produces g_V(partial), g_h, g_Q, g_K, g_Ksum.
// ---------------------------------------------------------------------------
__global__ __launch_bounds__(288,2) void k_front(
    const float* __restrict__ x,
    const float* __restrict__ q_w, const float* __restrict__ q_b,
    const float* __restrict__ k_w, const float* __restrict__ k_b,
    const float* __restrict__ v_w, const float* __restrict__ v_b,
    const float* __restrict__ fc1_w, const float* __restrict__ fc1_bn)
{
    extern __shared__ float sm[];
    float* s_Wt   = sm;                 // [64][144] k-major, o contiguous
    float* s_X    = sm + 64*144;        // [64][128] k-major, pixels contiguous
    float* s_vb   = s_X + 64*TP;        // 64
    float* s_finv = s_vb + 64;          // 64
    float* s_fbeta= s_finv + 64;        // 64
    float* s_qb   = s_fbeta + 64;       // 8
    float* s_kb   = s_qb + 8;           // 8

    int tid = threadIdx.x;
    int b  = blockIdx.y;
    int n0 = blockIdx.x * TP;

    // Weights, transposed into smem
    for (int i=tid;i<64*64;i+=288){
        int o=i>>6, c=i&63;
        s_Wt[c*144 + o]       = v_w[i];
        s_Wt[c*144 + 64 + o]  = fc1_w[i];
    }
    for (int i=tid;i<8*64;i+=288){
        int o=i>>6, c=i&63;
        s_Wt[c*144 + 128 + o] = q_w[i];
        s_Wt[c*144 + 136 + o] = k_w[i];
    }
    if (tid < 64){
        s_vb[tid] = v_b[tid];
        float sc=fc1_bn[0*CC+tid], bi=fc1_bn[1*CC+tid];
        float mn=fc1_bn[2*CC+tid], vr=fc1_bn[3*CC+tid];
        float inv = sc*rsqrtf(vr+1e-5f);
        s_finv[tid]=inv; s_fbeta[tid]=bi-mn*inv;
    } else if (tid < 72){
        s_qb[tid-64] = q_b[tid-64];
        s_kb[tid-64] = k_b[tid-64];
    }

    // X tile (coalesced float4)
    const float* xb = x + (size_t)b*CC*NN + n0;
    for (int i=tid;i<64*(TP/4);i+=288){
        int c = i>>5, p = i&31;
        ((float4*)s_X)[c*(TP/4)+p] = ((const float4*)(xb + (size_t)c*NN))[p];
    }
    __syncthreads();

    int tx = tid & 31, ty = tid / 32;   // ty 0..8
    float4 acc[16];
    #pragma unroll
    for (int i=0;i<16;i++) acc[i] = make_float4(0.f,0.f,0.f,0.f);

    const float4* X4 = (const float4*)s_X;
    #pragma unroll 4
    for (int k=0;k<64;k++){
        float4 xv = X4[k*(TP/4) + tx];
        const float4* wr = (const float4*)(s_Wt + k*144 + ty*16);
        float4 w0 = wr[0], w1 = wr[1], w2 = wr[2], w3 = wr[3];
        STEP(0,w0.x)  STEP(1,w0.y)  STEP(2,w0.z)  STEP(3,w0.w)
        STEP(4,w1.x)  STEP(5,w1.y)  STEP(6,w1.z)  STEP(7,w1.w)
        STEP(8,w2.x)  STEP(9,w2.y)  STEP(10,w2.z) STEP(11,w2.w)
        STEP(12,w3.x) STEP(13,w3.y) STEP(14,w3.z) STEP(15,w3.w)
    }

    size_t pix = (size_t)n0 + tx*4;
    if (ty < 4){
        // V partial = conv + bias
        #pragma unroll
        for (int i=0;i<16;i++){
            int o = ty*16 + i;
            float4 r = acc[i]; float bv = s_vb[o];
            r.x += bv; r.y += bv; r.z += bv; r.w += bv;
            *((float4*)(g_V + ((size_t)b*CC + o)*NN + pix)) = r;
        }
    } else if (ty < 8){
        // h = relu6(bn(fc1))
        #pragma unroll
        for (int i=0;i<16;i++){
            int o = (ty-4)*16 + i;
            float4 r = acc[i]; float iv = s_finv[o], be = s_fbeta[o];
            r.x = relu6f(r.x*iv+be); r.y = relu6f(r.y*iv+be);
            r.z = relu6f(r.z*iv+be); r.w = relu6f(r.w*iv+be);
            *((float4*)(g_h + ((size_t)b*CC + o)*NN + pix)) = r;
        }
    } else {
        // Q (i 0..7), K (i 8..15), Ksum
        #pragma unroll
        for (int i=0;i<8;i++){
            float4 r = acc[i]; float bq = s_qb[i];
            r.x = softplusf(r.x+bq); r.y = softplusf(r.y+bq);
            r.z = softplusf(r.z+bq); r.w = softplusf(r.w+bq);
            *((float4*)(g_Q + ((size_t)b*MM + i)*NN + pix)) = r;
        }
        float ks[8];
        #pragma unroll
        for (int i=0;i<8;i++){
            float4 r = acc[8+i]; float bk = s_kb[i];
            r.x = softplusf(r.x+bk); r.y = softplusf(r.y+bk);
            r.z = softplusf(r.z+bk); r.w = softplusf(r.w+bk);
            *((float4*)(g_K + ((size_t)b*MM + i)*NN + pix)) = r;
            ks[i] = r.x + r.y + r.z + r.w;
        }
        #pragma unroll
        for (int m=0;m<8;m++){
            float v = ks[m];
            #pragma unroll
            for (int off=16;off;off>>=1) v += __shfl_down_sync(0xffffffffu, v, off);
            if (tx==0) atomicAdd(&g_Ksum[b*MM+m], v);
        }
    }
}

// ---------------------------------------------------------------------------
// K2: depthwise 5x5 + 3x3 (both BN+ReLU6), summed -> g_s
// ---------------------------------------------------------------------------
__global__ __launch_bounds__(256) void k_dw(
    const float* __restrict__ w5, const float* __restrict__ bn5,
    const float* __restrict__ w3, const float* __restrict__ bn3)
{
    int bc = blockIdx.z;           // b*CC + c
    int c  = bc & (CC-1);
    int y0 = blockIdx.y*8, x0 = blockIdx.x*32;

    __shared__ float t[12][36];
    __shared__ float s_w5[25], s_w3[9], s_c[4];

    int tid = threadIdx.y*32 + threadIdx.x;
    const float* plane = g_h + (size_t)bc*NN;

    for (int i=tid;i<12*36;i+=256){
        int ly=i/36, lx=i%36;
        int gy=y0+ly-2, gx=x0+lx-2;
        float v = 0.f;
        if (gy>=0 && gy<HH && gx>=0 && gx<WW) v = plane[gy*WW+gx];
        t[ly][lx] = v;
    }
    if (tid<25) s_w5[tid] = w5[c*25+tid];
    if (tid<9)  s_w3[tid] = w3[c*9+tid];
    if (tid==0){
        float inv = bn5[0*CC+c]*rsqrtf(bn5[3*CC+c]+1e-5f);
        s_c[0]=inv; s_c[1]=bn5[1*CC+c]-bn5[2*CC+c]*inv;
    }
    if (tid==32){
        float inv = bn3[0*CC+c]*rsqrtf(bn3[3*CC+c]+1e-5f);
        s_c[2]=inv; s_c[3]=bn3[1*CC+c]-bn3[2*CC+c]*inv;
    }
    __syncthreads();

    int ty=threadIdx.y, tx=threadIdx.x;
    float a5=0.f;
    #pragma unroll
    for (int i=0;i<5;i++)
        #pragma unroll
        for (int j=0;j<5;j++)
            a5 = fmaf(s_w5[i*5+j], t[ty+i][tx+j], a5);
    float a3=0.f;
    #pragma unroll
    for (int i=0;i<3;i++)
        #pragma unroll
        for (int j=0;j<3;j++)
            a3 = fmaf(s_w3[i*3+j], t[ty+1+i][tx+1+j], a3);

    float r = relu6f(a5*s_c[0]+s_c[1]) + relu6f(a3*s_c[2]+s_c[3]);
    g_s[(size_t)bc*NN + (y0+ty)*WW + (x0+tx)] = r;
}

// ---------------------------------------------------------------------------
// K3: tiled GEMM fc2; V += relu6(bn(fc2(s)))  (in place)
// Block: 256 threads, ty = output-group of 8, tx = pixel/4
// ---------------------------------------------------------------------------
__global__ __launch_bounds__(256,4) void k_fc2(
    const float* __restrict__ fc2_w, const float* __restrict__ fc2_bn)
{
    extern __shared__ float sm[];
    float* s_Wt   = sm;              // [64][64] k-major, o contiguous
    float* s_X    = sm + 64*64;      // [64][128]
    float* s_inv  = s_X + 64*TP;     // 64
    float* s_beta = s_inv + 64;      // 64

    int tid = threadIdx.x;
    int b  = blockIdx.y;
    int n0 = blockIdx.x * TP;

    for (int i=tid;i<64*64;i+=256){
        int o=i>>6, c=i&63;
        s_Wt[c*64 + o] = fc2_w[i];
    }
    if (tid < 64){
        float sc=fc2_bn[0*CC+tid], bi=fc2_bn[1*CC+tid];
        float mn=fc2_bn[2*CC+tid], vr=fc2_bn[3*CC+tid];
        float inv = sc*rsqrtf(vr+1e-5f);
        s_inv[tid]=inv; s_beta[tid]=bi-mn*inv;
    }
    const float* sp = g_s + (size_t)b*CC*NN + n0;
    for (int i=tid;i<64*(TP/4);i+=256){
        int c = i>>5, p = i&31;
        ((float4*)s_X)[c*(TP/4)+p] = ((const float4*)(sp + (size_t)c*NN))[p];
    }
    __syncthreads();

    int tx = tid & 31, ty = tid >> 5;   // ty 0..7
    float4 acc[8];
    #pragma unroll
    for (int i=0;i<8;i++) acc[i] = make_float4(0.f,0.f,0.f,0.f);

    const float4* X4 = (const float4*)s_X;
    #pragma unroll 4
    for (int k=0;k<64;k++){
        float4 xv = X4[k*(TP/4) + tx];
        const float4* wr = (const float4*)(s_Wt + k*64 + ty*8);
        float4 w0 = wr[0], w1 = wr[1];
        STEP(0,w0.x) STEP(1,w0.y) STEP(2,w0.z) STEP(3,w0.w)
        STEP(4,w1.x) STEP(5,w1.y) STEP(6,w1.z) STEP(7,w1.w)
    }

    size_t pix = (size_t)n0 + tx*4;
    #pragma unroll
    for (int i=0;i<8;i++){
        int o = ty*8 + i;
        float iv = s_inv[o], be = s_beta[o];
        float4* vp = (float4*)(g_V + ((size_t)b*CC + o)*NN + pix);
        float4 v = *vp;
        v.x += relu6f(acc[i].x*iv+be); v.y += relu6f(acc[i].y*iv+be);
        v.z += relu6f(acc[i].z*iv+be); v.w += relu6f(acc[i].w*iv+be);
        *vp = v;
    }
}

// ---------------------------------------------------------------------------
// K4: KV[b,m,c] = sum_n K[b,m,n]*V[b,c,n]  (tiled smem, global atomics)
// ---------------------------------------------------------------------------
__global__ __launch_bounds__(256) void k_kv()
{
    int blk = blockIdx.x;
    int b  = blk / (NN/TN);
    int n0 = (blk % (NN/TN)) * TN;

    __shared__ float Vs[CC][TN+1];   // +1 pad: conflict-free column reads
    __shared__ float Ks[MM][TN];

    int tid = threadIdx.x;
    const float* Vb = g_V + (size_t)b*CC*NN + n0;
    for (int i=tid;i<CC*TN;i+=256){ int c=i/TN, n=i%TN; Vs[c][n]=Vb[(size_t)c*NN+n]; }
    const float* Kb = g_K + (size_t)b*MM*NN + n0;
    for (int i=tid;i<MM*TN;i+=256){ int m=i/TN, n=i%TN; Ks[m][n]=Kb[(size_t)m*NN+n]; }
    __syncthreads();

    int m = tid>>6;       // 0..3
    int c = tid & 63;     // 0..63
    float a0=0.f, a1=0.f;
    #pragma unroll 8
    for (int n=0;n<TN;n++){
        float vv = Vs[c][n];
        a0 = fmaf(Ks[m  ][n], vv, a0);
        a1 = fmaf(Ks[m+4][n], vv, a1);
    }
    atomicAdd(&g_KV[b*MM*CC + m*CC     + c], a0);
    atomicAdd(&g_KV[b*MM*CC + (m+4)*CC + c], a1);
}

// ---------------------------------------------------------------------------
// K5: out[b,c,n] = x + gamma * (sum_m Q[m,n]*KV[m,c]) / (sum_m Q[m,n]*(Ksum[m]+eps))
// ---------------------------------------------------------------------------
__global__ __launch_bounds__(256) void k_out(
    const float* __restrict__ x, const float* __restrict__ gamma,
    float* __restrict__ out)
{
    __shared__ __align__(16) float s_kv[MM*CC];
    __shared__ float s_ks[MM];
    int tid = threadIdx.x;
    int p = blockIdx.x*256 + tid;
    int b = p/NN, n = p%NN;     // NN % 256 == 0 -> b is block-uniform

    for (int i=tid;i<MM*CC;i+=256) s_kv[i] = g_KV[b*MM*CC + i];
    if (tid<MM) s_ks[tid] = g_Ksum[b*MM+tid] + 1e-6f;
    __syncthreads();

    float q[MM];
    #pragma unroll
    for (int m=0;m<MM;m++) q[m] = g_Q[(size_t)b*MM*NN + (size_t)m*NN + n];

    float den=0.f;
    #pragma unroll
    for (int m=0;m<MM;m++) den = fmaf(q[m], s_ks[m], den);
    float gs = gamma[0] / den;

    const float* xb = x + (size_t)b*CC*NN + n;
    float* ob = out + (size_t)b*CC*NN + n;

    const float4* kv4 = (const float4*)s_kv;
    #pragma unroll 4
    for (int c4=0;c4<16;c4++){
        float ax=0.f, ay=0.f, az=0.f, aw=0.f;
        #pragma unroll
        for (int m=0;m<MM;m++){
            float4 w = kv4[m*16+c4];
            ax = fmaf(q[m], w.x, ax); ay = fmaf(q[m], w.y, ay);
            az = fmaf(q[m], w.z, az); aw = fmaf(q[m], w.w, aw);
        }
        int c = 4*c4;
        ob[(size_t)(c+0)*NN] = xb[(size_t)(c+0)*NN] + gs*ax;
        ob[(size_t)(c+1)*NN] = xb[(size_t)(c+1)*NN] + gs*ay;
        ob[(size_t)(c+2)*NN] = xb[(size_t)(c+2)*NN] + gs*az;
        ob[(size_t)(c+3)*NN] = xb[(size_t)(c+3)*NN] + gs*aw;
    }
}

// ---------------------------------------------------------------------------
extern "C" void kernel_launch(void* const* d_in, const int* in_sizes, int n_in,
                              void* d_out, int out_size)
{
    const float* x      = (const float*)d_in[0];
    const float* gamma  = (const float*)d_in[1];
    const float* q_w    = (const float*)d_in[2];
    const float* q_b    = (const float*)d_in[3];
    const float* k_w    = (const float*)d_in[4];
    const float* k_b    = (const float*)d_in[5];
    const float* v_w    = (const float*)d_in[6];
    const float* v_b    = (const float*)d_in[7];
    const float* fc1_w  = (const float*)d_in[8];
    const float* fc1_bn = (const float*)d_in[9];
    const float* c1_w   = (const float*)d_in[10];
    const float* c1_bn  = (const float*)d_in[11];
    const float* c2_w   = (const float*)d_in[12];
    const float* c2_bn  = (const float*)d_in[13];
    const float* fc2_w  = (const float*)d_in[14];
    const float* fc2_bn = (const float*)d_in[15];
    float* out = (float*)d_out;

    const int smem_front = (64*144 + 64*TP + 64*3 + 16) * 4;
    const int smem_fc2   = (64*64 + 64*TP + 128) * 4;
    cudaFuncSetAttribute(k_front, cudaFuncAttributeMaxDynamicSharedMemorySize, smem_front);
    cudaFuncSetAttribute(k_fc2,   cudaFuncAttributeMaxDynamicSharedMemorySize, smem_fc2);

    k_zero<<<8,256>>>();
    k_front<<<dim3(NN/TP,BB),288,smem_front>>>(x,q_w,q_b,k_w,k_b,v_w,v_b,fc1_w,fc1_bn);
    k_dw<<<dim3(WW/32,HH/8,BB*CC),dim3(32,8)>>>(c1_w,c1_bn,c2_w,c2_bn);
    k_fc2<<<dim3(NN/TP,BB),256,smem_fc2>>>(fc2_w,fc2_bn);
    k_kv<<<BB*(NN/TN),256>>>();
    k_out<<<BN/256,256>>>(x,gamma,out);
}

// round 3
// speedup vs baseline: 1.1131x; 1.0171x over previous
#include <cuda_runtime.h>
#include <math.h>

#define BB 4
#define CC 64
#define MM 8
#define HH 224
#define WW 224
#define NN (HH*WW)      // 50176
#define BN (BB*NN)      // 200704
#define TN 128          // KV n-chunk (== TP)
#define TP 128          // GEMM pixel tile

// Scratch (static device globals — allocation-free per harness rules)
__device__ float g_h[BB*CC*NN];
__device__ float g_s[BB*CC*NN];
__device__ float g_V[BB*CC*NN];   // V partial (v-conv + bias) from front
__device__ float g_Q[BB*MM*NN];
__device__ float g_K[BB*MM*NN];
__device__ float g_KV[BB*MM*CC];
__device__ float g_Ksum[BB*MM];

typedef unsigned long long u64;

__device__ __forceinline__ float relu6f(float x){ return fminf(fmaxf(x,0.f),6.f); }
__device__ __forceinline__ float softplusf(float x){
    return fmaxf(x,0.f) + log1pf(expf(-fabsf(x)));
}
__device__ __forceinline__ u64 pack2(float x){
    u64 r; unsigned xi = __float_as_uint(x);
    asm("mov.b64 %0, {%1, %1};" : "=l"(r) : "r"(xi));
    return r;
}
__device__ __forceinline__ u64 ffma2(u64 a, u64 b, u64 c){
    u64 d; asm("fma.rn.f32x2 %0, %1, %2, %3;" : "=l"(d) : "l"(a), "l"(b), "l"(c));
    return d;
}
__device__ __forceinline__ float2 unpk(u64 a){
    float2 f; asm("mov.b64 {%0, %1}, %2;" : "=f"(f.x), "=f"(f.y) : "l"(a));
    return f;
}

__global__ void k_zero(){
    int i = blockIdx.x*blockDim.x + threadIdx.x;
    if (i < BB*MM*CC) g_KV[i]   = 0.f;
    if (i < BB*MM)    g_Ksum[i] = 0.f;
}

// ---------------------------------------------------------------------------
// K1 front: tiled GEMM (f32x2), 144 outputs = [v(64) | fc1(64) | q(8) | k(8)], K=64.
// Block: 288 threads (9 warps). ty = warp = output-group of 16 (8 pairs); tx = pixel/4.
// ---------------------------------------------------------------------------
__global__ __launch_bounds__(288,2) void k_front(
    const float* __restrict__ x,
    const float* __restrict__ q_w, const float* __restrict__ q_b,
    const float* __restrict__ k_w, const float* __restrict__ k_b,
    const float* __restrict__ v_w, const float* __restrict__ v_b,
    const float* __restrict__ fc1_w, const float* __restrict__ fc1_bn)
{
    extern __shared__ float sm[];
    float* s_Wt   = sm;                 // [64][144] k-major, o contiguous
    float* s_X    = sm + 64*144;        // [64][128] k-major, pixels contiguous
    float* s_vb   = s_X + 64*TP;        // 64
    float* s_finv = s_vb + 64;          // 64
    float* s_fbeta= s_finv + 64;        // 64
    float* s_qb   = s_fbeta + 64;       // 8
    float* s_kb   = s_qb + 8;           // 8

    int tid = threadIdx.x;
    int b  = blockIdx.y;
    int n0 = blockIdx.x * TP;

    for (int i=tid;i<64*64;i+=288){
        int o=i>>6, c=i&63;
        s_Wt[c*144 + o]       = v_w[i];
        s_Wt[c*144 + 64 + o]  = fc1_w[i];
    }
    for (int i=tid;i<8*64;i+=288){
        int o=i>>6, c=i&63;
        s_Wt[c*144 + 128 + o] = q_w[i];
        s_Wt[c*144 + 136 + o] = k_w[i];
    }
    if (tid < 64){
        s_vb[tid] = v_b[tid];
        float sc=fc1_bn[0*CC+tid], bi=fc1_bn[1*CC+tid];
        float mn=fc1_bn[2*CC+tid], vr=fc1_bn[3*CC+tid];
        float inv = sc*rsqrtf(vr+1e-5f);
        s_finv[tid]=inv; s_fbeta[tid]=bi-mn*inv;
    } else if (tid < 72){
        s_qb[tid-64] = q_b[tid-64];
        s_kb[tid-64] = k_b[tid-64];
    }

    const float* xb = x + (size_t)b*CC*NN + n0;
    for (int i=tid;i<64*(TP/4);i+=288){
        int c = i>>5, p = i&31;
        ((float4*)s_X)[c*(TP/4)+p] = ((const float4*)(xb + (size_t)c*NN))[p];
    }
    __syncthreads();

    int tx = tid & 31, ty = tid / 32;   // ty 0..8

    u64 acc[8][4];
    #pragma unroll
    for (int j=0;j<8;j++)
        #pragma unroll
        for (int p=0;p<4;p++) acc[j][p] = 0ull;

    const float4* X4 = (const float4*)s_X;
    #pragma unroll 2
    for (int k=0;k<64;k++){
        float4 xv = X4[k*(TP/4) + tx];
        u64 xx0 = pack2(xv.x), xx1 = pack2(xv.y), xx2 = pack2(xv.z), xx3 = pack2(xv.w);
        const ulonglong2* wr = (const ulonglong2*)(s_Wt + k*144 + ty*16);
        ulonglong2 wA = wr[0], wB = wr[1], wC = wr[2], wD = wr[3];
        #define FST(j, wp) { acc[j][0]=ffma2(xx0,wp,acc[j][0]); acc[j][1]=ffma2(xx1,wp,acc[j][1]); \
                             acc[j][2]=ffma2(xx2,wp,acc[j][2]); acc[j][3]=ffma2(xx3,wp,acc[j][3]); }
        FST(0,wA.x) FST(1,wA.y) FST(2,wB.x) FST(3,wB.y)
        FST(4,wC.x) FST(5,wC.y) FST(6,wD.x) FST(7,wD.y)
        #undef FST
    }

    size_t pix = (size_t)n0 + tx*4;
    if (ty < 4){
        #pragma unroll
        for (int j=0;j<8;j++){
            int o0 = ty*16 + 2*j, o1 = o0+1;
            float2 u0=unpk(acc[j][0]), u1=unpk(acc[j][1]), u2=unpk(acc[j][2]), u3=unpk(acc[j][3]);
            float b0 = s_vb[o0], b1 = s_vb[o1];
            float4 r0 = make_float4(u0.x+b0, u1.x+b0, u2.x+b0, u3.x+b0);
            float4 r1 = make_float4(u0.y+b1, u1.y+b1, u2.y+b1, u3.y+b1);
            *((float4*)(g_V + ((size_t)b*CC + o0)*NN + pix)) = r0;
            *((float4*)(g_V + ((size_t)b*CC + o1)*NN + pix)) = r1;
        }
    } else if (ty < 8){
        #pragma unroll
        for (int j=0;j<8;j++){
            int o0 = (ty-4)*16 + 2*j, o1 = o0+1;
            float2 u0=unpk(acc[j][0]), u1=unpk(acc[j][1]), u2=unpk(acc[j][2]), u3=unpk(acc[j][3]);
            float i0 = s_finv[o0], e0 = s_fbeta[o0];
            float i1 = s_finv[o1], e1 = s_fbeta[o1];
            float4 r0 = make_float4(relu6f(u0.x*i0+e0), relu6f(u1.x*i0+e0),
                                    relu6f(u2.x*i0+e0), relu6f(u3.x*i0+e0));
            float4 r1 = make_float4(relu6f(u0.y*i1+e1), relu6f(u1.y*i1+e1),
                                    relu6f(u2.y*i1+e1), relu6f(u3.y*i1+e1));
            *((float4*)(g_h + ((size_t)b*CC + o0)*NN + pix)) = r0;
            *((float4*)(g_h + ((size_t)b*CC + o1)*NN + pix)) = r1;
        }
    } else {
        float ks[8];
        #pragma unroll
        for (int j=0;j<8;j++){
            // j<4: q pairs (outputs 2j,2j+1); j>=4: k pairs (outputs 2j-8, 2j-7)
            float2 u0=unpk(acc[j][0]), u1=unpk(acc[j][1]), u2=unpk(acc[j][2]), u3=unpk(acc[j][3]);
            if (j < 4){
                int m0 = 2*j, m1 = m0+1;
                float bq0 = s_qb[m0], bq1 = s_qb[m1];
                float4 r0 = make_float4(softplusf(u0.x+bq0), softplusf(u1.x+bq0),
                                        softplusf(u2.x+bq0), softplusf(u3.x+bq0));
                float4 r1 = make_float4(softplusf(u0.y+bq1), softplusf(u1.y+bq1),
                                        softplusf(u2.y+bq1), softplusf(u3.y+bq1));
                *((float4*)(g_Q + ((size_t)b*MM + m0)*NN + pix)) = r0;
                *((float4*)(g_Q + ((size_t)b*MM + m1)*NN + pix)) = r1;
            } else {
                int m0 = 2*j-8, m1 = m0+1;
                float bk0 = s_kb[m0], bk1 = s_kb[m1];
                float4 r0 = make_float4(softplusf(u0.x+bk0), softplusf(u1.x+bk0),
                                        softplusf(u2.x+bk0), softplusf(u3.x+bk0));
                float4 r1 = make_float4(softplusf(u0.y+bk1), softplusf(u1.y+bk1),
                                        softplusf(u2.y+bk1), softplusf(u3.y+bk1));
                *((float4*)(g_K + ((size_t)b*MM + m0)*NN + pix)) = r0;
                *((float4*)(g_K + ((size_t)b*MM + m1)*NN + pix)) = r1;
                ks[m0] = r0.x+r0.y+r0.z+r0.w;
                ks[m1] = r1.x+r1.y+r1.z+r1.w;
            }
        }
        #pragma unroll
        for (int m=0;m<8;m++){
            float v = ks[m];
            #pragma unroll
            for (int off=16;off;off>>=1) v += __shfl_down_sync(0xffffffffu, v, off);
            if (tx==0) atomicAdd(&g_Ksum[b*MM+m], v);
        }
    }
}

// ---------------------------------------------------------------------------
// K2: depthwise 5x5 + 3x3 (both BN+ReLU6), summed -> g_s
// ---------------------------------------------------------------------------
__global__ __launch_bounds__(256) void k_dw(
    const float* __restrict__ w5, const float* __restrict__ bn5,
    const float* __restrict__ w3, const float* __restrict__ bn3)
{
    int bc = blockIdx.z;           // b*CC + c
    int c  = bc & (CC-1);
    int y0 = blockIdx.y*8, x0 = blockIdx.x*32;

    __shared__ float t[12][36];
    __shared__ float s_w5[25], s_w3[9], s_c[4];

    int tid = threadIdx.y*32 + threadIdx.x;
    const float* plane = g_h + (size_t)bc*NN;

    for (int i=tid;i<12*36;i+=256){
        int ly=i/36, lx=i%36;
        int gy=y0+ly-2, gx=x0+lx-2;
        float v = 0.f;
        if (gy>=0 && gy<HH && gx>=0 && gx<WW) v = plane[gy*WW+gx];
        t[ly][lx] = v;
    }
    if (tid<25) s_w5[tid] = w5[c*25+tid];
    if (tid<9)  s_w3[tid] = w3[c*9+tid];
    if (tid==0){
        float inv = bn5[0*CC+c]*rsqrtf(bn5[3*CC+c]+1e-5f);
        s_c[0]=inv; s_c[1]=bn5[1*CC+c]-bn5[2*CC+c]*inv;
    }
    if (tid==32){
        float inv = bn3[0*CC+c]*rsqrtf(bn3[3*CC+c]+1e-5f);
        s_c[2]=inv; s_c[3]=bn3[1*CC+c]-bn3[2*CC+c]*inv;
    }
    __syncthreads();

    int ty=threadIdx.y, tx=threadIdx.x;
    float a5=0.f;
    #pragma unroll
    for (int i=0;i<5;i++)
        #pragma unroll
        for (int j=0;j<5;j++)
            a5 = fmaf(s_w5[i*5+j], t[ty+i][tx+j], a5);
    float a3=0.f;
    #pragma unroll
    for (int i=0;i<3;i++)
        #pragma unroll
        for (int j=0;j<3;j++)
            a3 = fmaf(s_w3[i*3+j], t[ty+1+i][tx+1+j], a3);

    float r = relu6f(a5*s_c[0]+s_c[1]) + relu6f(a3*s_c[2]+s_c[3]);
    g_s[(size_t)bc*NN + (y0+ty)*WW + (x0+tx)] = r;
}

// ---------------------------------------------------------------------------
// K3: fused fc2 + KV.
//   xc = relu6(bn(fc2(s)));  V = g_V(partial) + xc  (registers -> smem only)
//   KV[b,m,c] += sum_n K[b,m,n]*V[c,n]  (block-local tile, global atomics)
// Block: 256 threads, ty = output-group of 8 (4 pairs), tx = pixel/4
// ---------------------------------------------------------------------------
__global__ __launch_bounds__(256,3) void k_fc2kv(
    const float* __restrict__ fc2_w, const float* __restrict__ fc2_bn)
{
    extern __shared__ float sm[];
    float* s_Wt   = sm;               // [64][64] k-major, o contiguous (16KB)
    float* s_X    = sm + 64*64;       // [64][128] (32KB)
    // reuse region after mainloop:
    float* s_Vp   = sm;               // [64][129] padded (33KB)
    float* s_Kt   = sm + 64*(TN+1);   // [8][128]  (4KB)
    float* s_inv  = sm + 64*64 + 64*TP;   // 64 (outside reuse: 48K..)
    float* s_beta = s_inv + 64;           // 64

    int tid = threadIdx.x;
    int b  = blockIdx.y;
    int n0 = blockIdx.x * TP;

    for (int i=tid;i<64*64;i+=256){
        int o=i>>6, c=i&63;
        s_Wt[c*64 + o] = fc2_w[i];
    }
    if (tid < 64){
        float sc=fc2_bn[0*CC+tid], bi=fc2_bn[1*CC+tid];
        float mn=fc2_bn[2*CC+tid], vr=fc2_bn[3*CC+tid];
        float inv = sc*rsqrtf(vr+1e-5f);
        s_inv[tid]=inv; s_beta[tid]=bi-mn*inv;
    }
    const float* sp = g_s + (size_t)b*CC*NN + n0;
    for (int i=tid;i<64*(TP/4);i+=256){
        int c = i>>5, p = i&31;
        ((float4*)s_X)[c*(TP/4)+p] = ((const float4*)(sp + (size_t)c*NN))[p];
    }
    __syncthreads();

    int tx = tid & 31, ty = tid >> 5;   // ty 0..7
    u64 acc[4][4];
    #pragma unroll
    for (int j=0;j<4;j++)
        #pragma unroll
        for (int p=0;p<4;p++) acc[j][p] = 0ull;

    const float4* X4 = (const float4*)s_X;
    #pragma unroll 4
    for (int k=0;k<64;k++){
        float4 xv = X4[k*(TP/4) + tx];
        u64 xx0 = pack2(xv.x), xx1 = pack2(xv.y), xx2 = pack2(xv.z), xx3 = pack2(xv.w);
        const ulonglong2* wr = (const ulonglong2*)(s_Wt + k*64 + ty*8);
        ulonglong2 wA = wr[0], wB = wr[1];
        #define FST(j, wp) { acc[j][0]=ffma2(xx0,wp,acc[j][0]); acc[j][1]=ffma2(xx1,wp,acc[j][1]); \
                             acc[j][2]=ffma2(xx2,wp,acc[j][2]); acc[j][3]=ffma2(xx3,wp,acc[j][3]); }
        FST(0,wA.x) FST(1,wA.y) FST(2,wB.x) FST(3,wB.y)
        #undef FST
    }

    // V_final per thread: outputs ty*8+2j(+1), pixels tx*4..+3
    size_t pix = (size_t)n0 + tx*4;
    float4 vf0[4], vf1[4];
    #pragma unroll
    for (int j=0;j<4;j++){
        int o0 = ty*8 + 2*j, o1 = o0+1;
        float2 u0=unpk(acc[j][0]), u1=unpk(acc[j][1]), u2=unpk(acc[j][2]), u3=unpk(acc[j][3]);
        float i0=s_inv[o0], e0=s_beta[o0], i1=s_inv[o1], e1=s_beta[o1];
        float4 v0 = *((const float4*)(g_V + ((size_t)b*CC + o0)*NN + pix));
        float4 v1 = *((const float4*)(g_V + ((size_t)b*CC + o1)*NN + pix));
        v0.x += relu6f(u0.x*i0+e0); v0.y += relu6f(u1.x*i0+e0);
        v0.z += relu6f(u2.x*i0+e0); v0.w += relu6f(u3.x*i0+e0);
        v1.x += relu6f(u0.y*i1+e1); v1.y += relu6f(u1.y*i1+e1);
        v1.z += relu6f(u2.y*i1+e1); v1.w += relu6f(u3.y*i1+e1);
        vf0[j]=v0; vf1[j]=v1;
    }

    __syncthreads();   // done reading s_Wt / s_X

    // Stage V into padded smem + load K tile
    #pragma unroll
    for (int j=0;j<4;j++){
        int o0 = ty*8 + 2*j, o1 = o0+1;
        float* d0 = s_Vp + o0*(TN+1) + tx*4;
        float* d1 = s_Vp + o1*(TN+1) + tx*4;
        d0[0]=vf0[j].x; d0[1]=vf0[j].y; d0[2]=vf0[j].z; d0[3]=vf0[j].w;
        d1[0]=vf1[j].x; d1[1]=vf1[j].y; d1[2]=vf1[j].z; d1[3]=vf1[j].w;
    }
    {
        int m = tid >> 5, p = tid & 31;   // 256 threads = 8 rows x 32 float4
        ((float4*)s_Kt)[m*(TN/4)+p] =
            ((const float4*)(g_K + ((size_t)b*MM + m)*NN + n0))[p];
    }
    __syncthreads();

    // KV reduction (same structure as old k_kv)
    {
        int m = tid >> 6;        // 0..3
        int c = tid & 63;        // 0..63
        const float* Vr = s_Vp + c*(TN+1);
        float a0=0.f, a1=0.f;
        #pragma unroll 8
        for (int n=0;n<TN;n++){
            float vv = Vr[n];
            a0 = fmaf(s_Kt[ m     *TN + n], vv, a0);
            a1 = fmaf(s_Kt[(m+4)*TN + n], vv, a1);
        }
        atomicAdd(&g_KV[b*MM*CC + m*CC     + c], a0);
        atomicAdd(&g_KV[b*MM*CC + (m+4)*CC + c], a1);
    }
}

// ---------------------------------------------------------------------------
// K5: out[b,c,n] = x + gamma * (sum_m Q[m,n]*KV[m,c]) / (sum_m Q[m,n]*(Ksum[m]+eps))
// ---------------------------------------------------------------------------
__global__ __launch_bounds__(256) void k_out(
    const float* __restrict__ x, const float* __restrict__ gamma,
    float* __restrict__ out)
{
    __shared__ __align__(16) float s_kv[MM*CC];
    __shared__ float s_ks[MM];
    int tid = threadIdx.x;
    int p = blockIdx.x*256 + tid;
    int b = p/NN, n = p%NN;     // NN % 256 == 0 -> b is block-uniform

    for (int i=tid;i<MM*CC;i+=256) s_kv[i] = g_KV[b*MM*CC + i];
    if (tid<MM) s_ks[tid] = g_Ksum[b*MM+tid] + 1e-6f;
    __syncthreads();

    float q[MM];
    #pragma unroll
    for (int m=0;m<MM;m++) q[m] = g_Q[(size_t)b*MM*NN + (size_t)m*NN + n];

    float den=0.f;
    #pragma unroll
    for (int m=0;m<MM;m++) den = fmaf(q[m], s_ks[m], den);
    float gs = gamma[0] / den;

    const float* xb = x + (size_t)b*CC*NN + n;
    float* ob = out + (size_t)b*CC*NN + n;

    const float4* kv4 = (const float4*)s_kv;
    #pragma unroll 4
    for (int c4=0;c4<16;c4++){
        float ax=0.f, ay=0.f, az=0.f, aw=0.f;
        #pragma unroll
        for (int m=0;m<MM;m++){
            float4 w = kv4[m*16+c4];
            ax = fmaf(q[m], w.x, ax); ay = fmaf(q[m], w.y, ay);
            az = fmaf(q[m], w.z, az); aw = fmaf(q[m], w.w, aw);
        }
        int c = 4*c4;
        ob[(size_t)(c+0)*NN] = xb[(size_t)(c+0)*NN] + gs*ax;
        ob[(size_t)(c+1)*NN] = xb[(size_t)(c+1)*NN] + gs*ay;
        ob[(size_t)(c+2)*NN] = xb[(size_t)(c+2)*NN] + gs*az;
        ob[(size_t)(c+3)*NN] = xb[(size_t)(c+3)*NN] + gs*aw;
    }
}

// ---------------------------------------------------------------------------
extern "C" void kernel_launch(void* const* d_in, const int* in_sizes, int n_in,
                              void* d_out, int out_size)
{
    const float* x      = (const float*)d_in[0];
    const float* gamma  = (const float*)d_in[1];
    const float* q_w    = (const float*)d_in[2];
    const float* q_b    = (const float*)d_in[3];
    const float* k_w    = (const float*)d_in[4];
    const float* k_b    = (const float*)d_in[5];
    const float* v_w    = (const float*)d_in[6];
    const float* v_b    = (const float*)d_in[7];
    const float* fc1_w  = (const float*)d_in[8];
    const float* fc1_bn = (const float*)d_in[9];
    const float* c1_w   = (const float*)d_in[10];
    const float* c1_bn  = (const float*)d_in[11];
    const float* c2_w   = (const float*)d_in[12];
    const float* c2_bn  = (const float*)d_in[13];
    const float* fc2_w  = (const float*)d_in[14];
    const float* fc2_bn = (const float*)d_in[15];
    float* out = (float*)d_out;

    const int smem_front = (64*144 + 64*TP + 64*3 + 16) * 4;
    const int smem_fc2   = (64*64 + 64*TP + 128) * 4;
    cudaFuncSetAttribute(k_front,  cudaFuncAttributeMaxDynamicSharedMemorySize, smem_front);
    cudaFuncSetAttribute(k_fc2kv,  cudaFuncAttributeMaxDynamicSharedMemorySize, smem_fc2);

    k_zero<<<8,256>>>();
    k_front<<<dim3(NN/TP,BB),288,smem_front>>>(x,q_w,q_b,k_w,k_b,v_w,v_b,fc1_w,fc1_bn);
    k_dw<<<dim3(WW/32,HH/8,BB*CC),dim3(32,8)>>>(c1_w,c1_bn,c2_w,c2_bn);
    k_fc2kv<<<dim3(NN/TP,BB),256,smem_fc2>>>(fc2_w,fc2_bn);
    k_out<<<BN/256,256>>>(x,gamma,out);
}

// round 7
// speedup vs baseline: 1.2551x; 1.1276x over previous
#include <cuda_runtime.h>
#include <cuda_bf16.h>
#include <math.h>
#include <stdint.h>

#define BB 4
#define CC 64
#define MM 8
#define HH 224
#define WW 224
#define NN (HH*WW)      // 50176
#define BN (BB*NN)      // 200704
#define TPX 128         // pixels per CTA tile

// Scratch (static device globals — allocation-free per harness rules)
__device__ float g_h[BB*CC*NN];
__device__ float g_s[BB*CC*NN];
__device__ float g_V[BB*CC*NN];   // V partial (v-conv + bias) from front
__device__ float g_Q[BB*MM*NN];
__device__ float g_K[BB*MM*NN];
__device__ float g_KV[BB*MM*CC];
__device__ float g_Ksum[BB*MM];

__device__ __forceinline__ float relu6f(float x){ return fminf(fmaxf(x,0.f),6.f); }
__device__ __forceinline__ float softplusf(float x){
    return fmaxf(x,0.f) + log1pf(expf(-fabsf(x)));
}
__device__ __forceinline__ uint32_t smem_u32(const void* p){
    uint32_t a;
    asm("{ .reg .u64 t; cvta.to.shared.u64 t, %1; cvt.u32.u64 %0, t; }" : "=r"(a) : "l"(p));
    return a;
}
// split (v0,v1) into packed bf16x2 hi and lo parts (low half = v0)
__device__ __forceinline__ void bsplit2(float v0, float v1, uint32_t& hi, uint32_t& lo){
    __nv_bfloat162 h = __floats2bfloat162_rn(v0, v1);
    float r0 = v0 - __bfloat162float(__low2bfloat16(h));
    float r1 = v1 - __bfloat162float(__high2bfloat16(h));
    __nv_bfloat162 l = __floats2bfloat162_rn(r0, r1);
    hi = *(uint32_t*)&h; lo = *(uint32_t*)&l;
}
__device__ __forceinline__ void ldsm4(uint32_t* r, uint32_t a){
    asm volatile("ldmatrix.sync.aligned.m8n8.x4.shared.b16 {%0,%1,%2,%3}, [%4];"
        : "=r"(r[0]),"=r"(r[1]),"=r"(r[2]),"=r"(r[3]) : "r"(a));
}
__device__ __forceinline__ void ldsm4t(uint32_t* r, uint32_t a){
    asm volatile("ldmatrix.sync.aligned.m8n8.x4.trans.shared.b16 {%0,%1,%2,%3}, [%4];"
        : "=r"(r[0]),"=r"(r[1]),"=r"(r[2]),"=r"(r[3]) : "r"(a));
}
__device__ __forceinline__ void mma16816(float* d, const uint32_t* a, const uint32_t* b){
    asm volatile("mma.sync.aligned.m16n8k16.row.col.f32.bf16.bf16.f32 "
        "{%0,%1,%2,%3}, {%4,%5,%6,%7}, {%8,%9}, {%0,%1,%2,%3};"
        : "+f"(d[0]),"+f"(d[1]),"+f"(d[2]),"+f"(d[3])
        : "r"(a[0]),"r"(a[1]),"r"(a[2]),"r"(a[3]), "r"(b[0]),"r"(b[1]));
}

__global__ void k_zero(){
    int i = blockIdx.x*blockDim.x + threadIdx.x;
    if (i < BB*MM*CC) g_KV[i]   = 0.f;
    if (i < BB*MM)    g_Ksum[i] = 0.f;
}

// ---------------------------------------------------------------------------
// K1 front (mma.sync bf16-split): D[144 out, 128 px] = W[144,64] x Xt[64,128]
// outputs: [v(0..63) | fc1(64..127) | q(128..135) | k(136..143)]
// 288 threads = 9 warps; warp w = m16 tile (outputs 16w..16w+15).
// smem byte layout:
//   WHI 0 (20736 = 144*72*2), WLO 20736, XHI 41472 (17408 = 64*136*2),
//   XLO 58880, consts 76288..  total 77184
// ---------------------------------------------------------------------------
#define F_WHI 0
#define F_WLO 20736
#define F_XHI 41472
#define F_XLO 58880
#define F_CST 76288
#define F_SMEM 77184
#define WS 72     // weight smem row stride (bf16 elems)
#define XS 136    // x smem row stride (bf16 elems)

__global__ __launch_bounds__(288,2) void k_front(
    const float* __restrict__ x,
    const float* __restrict__ q_w, const float* __restrict__ q_b,
    const float* __restrict__ k_w, const float* __restrict__ k_b,
    const float* __restrict__ v_w, const float* __restrict__ v_b,
    const float* __restrict__ fc1_w, const float* __restrict__ fc1_bn)
{
    extern __shared__ char sm[];
    __nv_bfloat16* wHi = (__nv_bfloat16*)(sm + F_WHI);
    __nv_bfloat16* wLo = (__nv_bfloat16*)(sm + F_WLO);
    __nv_bfloat16* xHi = (__nv_bfloat16*)(sm + F_XHI);
    __nv_bfloat16* xLo = (__nv_bfloat16*)(sm + F_XLO);
    float* s_vb   = (float*)(sm + F_CST);         // 64
    float* s_finv = s_vb + 64;                    // 64
    float* s_fbeta= s_finv + 64;                  // 64
    float* s_qb   = s_fbeta + 64;                 // 8
    float* s_kb   = s_qb + 8;                     // 8
    uint32_t sb = smem_u32(sm);

    int tid = threadIdx.x;
    int b  = blockIdx.y;
    int n0 = blockIdx.x * TPX;

    // weights: 144 x 64, split + pack pairs
    for (int i=tid; i<144*32; i+=288){
        int o = i>>5, c2 = (i&31)<<1;
        const float* src = (o<64) ? v_w + o*64
                         : (o<128)? fc1_w + (o-64)*64
                         : (o<136)? q_w + (o-128)*64
                         :          k_w + (o-136)*64;
        uint32_t hi, lo; bsplit2(src[c2], src[c2+1], hi, lo);
        *(uint32_t*)(wHi + o*WS + c2) = hi;
        *(uint32_t*)(wLo + o*WS + c2) = lo;
    }
    // x tile: [64 ch][128 px]
    const float* xb = x + (size_t)b*CC*NN + n0;
    for (int i=tid; i<64*64; i+=288){
        int c = i>>6, p2 = (i&63)<<1;
        float2 v = *(const float2*)(xb + (size_t)c*NN + p2);
        uint32_t hi, lo; bsplit2(v.x, v.y, hi, lo);
        *(uint32_t*)(xHi + c*XS + p2) = hi;
        *(uint32_t*)(xLo + c*XS + p2) = lo;
    }
    if (tid < 64){
        s_vb[tid] = v_b[tid];
        float sc=fc1_bn[0*CC+tid], bi=fc1_bn[1*CC+tid];
        float mn=fc1_bn[2*CC+tid], vr=fc1_bn[3*CC+tid];
        float inv = sc*rsqrtf(vr+1e-5f);
        s_finv[tid]=inv; s_fbeta[tid]=bi-mn*inv;
    } else if (tid < 72){
        s_qb[tid-64] = q_b[tid-64];
        s_kb[tid-64] = k_b[tid-64];
    }
    __syncthreads();

    int w = tid >> 5, lane = tid & 31;
    int m0 = w*16;

    float acc[16][4];
    #pragma unroll
    for (int i=0;i<16;i++){ acc[i][0]=acc[i][1]=acc[i][2]=acc[i][3]=0.f; }

    int arow = m0 + (lane & 15), acol8 = (lane>>4)*8;
    int brow = (lane & 7) + 8*((lane>>3)&1), bcol8 = (lane>>4)*8;

    #pragma unroll
    for (int kt=0; kt<4; kt++){
        int k0 = kt*16;
        uint32_t aH[4], aL[4];
        uint32_t aaddr = sb + F_WHI + (uint32_t)(arow*WS + k0 + acol8)*2;
        ldsm4(aH, aaddr);
        ldsm4(aL, aaddr + (F_WLO - F_WHI));
        #pragma unroll
        for (int np=0; np<8; np++){
            uint32_t baddr = sb + F_XHI + (uint32_t)((k0+brow)*XS + np*16 + bcol8)*2;
            uint32_t bH[4], bL[4];
            ldsm4t(bH, baddr);
            ldsm4t(bL, baddr + (F_XLO - F_XHI));
            mma16816(acc[2*np],   aH, bH);
            mma16816(acc[2*np],   aL, bH);
            mma16816(acc[2*np],   aH, bL);
            mma16816(acc[2*np+1], aH, bH+2);
            mma16816(acc[2*np+1], aL, bH+2);
            mma16816(acc[2*np+1], aH, bL+2);
        }
    }

    int g = lane >> 2, t2 = (lane & 3)*2;
    if (w < 4){
        int o0 = m0 + g, o1 = o0 + 8;
        float b0 = s_vb[o0], b1 = s_vb[o1];
        float* p0 = g_V + ((size_t)b*CC + o0)*NN + n0 + t2;
        float* p1 = g_V + ((size_t)b*CC + o1)*NN + n0 + t2;
        #pragma unroll
        for (int nt=0; nt<16; nt++){
            *(float2*)(p0 + nt*8) = make_float2(acc[nt][0]+b0, acc[nt][1]+b0);
            *(float2*)(p1 + nt*8) = make_float2(acc[nt][2]+b1, acc[nt][3]+b1);
        }
    } else if (w < 8){
        int o0 = m0 - 64 + g, o1 = o0 + 8;
        float i0=s_finv[o0], e0=s_fbeta[o0], i1=s_finv[o1], e1=s_fbeta[o1];
        float* p0 = g_h + ((size_t)b*CC + o0)*NN + n0 + t2;
        float* p1 = g_h + ((size_t)b*CC + o1)*NN + n0 + t2;
        #pragma unroll
        for (int nt=0; nt<16; nt++){
            *(float2*)(p0 + nt*8) = make_float2(relu6f(acc[nt][0]*i0+e0), relu6f(acc[nt][1]*i0+e0));
            *(float2*)(p1 + nt*8) = make_float2(relu6f(acc[nt][2]*i1+e1), relu6f(acc[nt][3]*i1+e1));
        }
    } else {
        // rows g -> Q[m=g], rows g+8 -> K[m=g]
        float bq = s_qb[g], bk = s_kb[g];
        float* pq = g_Q + ((size_t)b*MM + g)*NN + n0 + t2;
        float* pk = g_K + ((size_t)b*MM + g)*NN + n0 + t2;
        float ksum = 0.f;
        #pragma unroll
        for (int nt=0; nt<16; nt++){
            float q0 = softplusf(acc[nt][0]+bq), q1 = softplusf(acc[nt][1]+bq);
            float k0v = softplusf(acc[nt][2]+bk), k1v = softplusf(acc[nt][3]+bk);
            *(float2*)(pq + nt*8) = make_float2(q0, q1);
            *(float2*)(pk + nt*8) = make_float2(k0v, k1v);
            ksum += k0v + k1v;
        }
        ksum += __shfl_xor_sync(0xffffffffu, ksum, 1);
        ksum += __shfl_xor_sync(0xffffffffu, ksum, 2);
        if ((lane & 3) == 0) atomicAdd(&g_Ksum[b*MM + g], ksum);
    }
}

// ---------------------------------------------------------------------------
// K2: depthwise 5x5 + 3x3 (both BN+ReLU6), summed -> g_s
// ---------------------------------------------------------------------------
__global__ __launch_bounds__(256) void k_dw(
    const float* __restrict__ w5, const float* __restrict__ bn5,
    const float* __restrict__ w3, const float* __restrict__ bn3)
{
    int bc = blockIdx.z;
    int c  = bc & (CC-1);
    int y0 = blockIdx.y*8, x0 = blockIdx.x*32;

    __shared__ float t[12][36];
    __shared__ float s_w5[25], s_w3[9], s_c[4];

    int tid = threadIdx.y*32 + threadIdx.x;
    const float* plane = g_h + (size_t)bc*NN;

    for (int i=tid;i<12*36;i+=256){
        int ly=i/36, lx=i%36;
        int gy=y0+ly-2, gx=x0+lx-2;
        float v = 0.f;
        if (gy>=0 && gy<HH && gx>=0 && gx<WW) v = plane[gy*WW+gx];
        t[ly][lx] = v;
    }
    if (tid<25) s_w5[tid] = w5[c*25+tid];
    if (tid<9)  s_w3[tid] = w3[c*9+tid];
    if (tid==0){
        float inv = bn5[0*CC+c]*rsqrtf(bn5[3*CC+c]+1e-5f);
        s_c[0]=inv; s_c[1]=bn5[1*CC+c]-bn5[2*CC+c]*inv;
    }
    if (tid==32){
        float inv = bn3[0*CC+c]*rsqrtf(bn3[3*CC+c]+1e-5f);
        s_c[2]=inv; s_c[3]=bn3[1*CC+c]-bn3[2*CC+c]*inv;
    }
    __syncthreads();

    int ty=threadIdx.y, tx=threadIdx.x;
    float a5=0.f;
    #pragma unroll
    for (int i=0;i<5;i++)
        #pragma unroll
        for (int j=0;j<5;j++)
            a5 = fmaf(s_w5[i*5+j], t[ty+i][tx+j], a5);
    float a3=0.f;
    #pragma unroll
    for (int i=0;i<3;i++)
        #pragma unroll
        for (int j=0;j<3;j++)
            a3 = fmaf(s_w3[i*3+j], t[ty+1+i][tx+1+j], a3);

    float r = relu6f(a5*s_c[0]+s_c[1]) + relu6f(a3*s_c[2]+s_c[3]);
    g_s[(size_t)bc*NN + (y0+ty)*WW + (x0+tx)] = r;
}

// ---------------------------------------------------------------------------
// K3: fc2 (mma.sync bf16-split) + fused KV.
// D[64 out, 128 px] = W[64,64] x St[64,128]; xc=relu6(bn(D)); V=g_V+xc -> smem
// then KV[b,m,c] += sum_n K*V with atomics.
// 256 threads = 8 warps: mt = w&3 (out tile), ph = w>>2 (px half)
// smem bytes: AHI 0 (9216=64*72*2), ALO 9216, XHI 18432 (17408), XLO 35840,
//             KT 53248 (4096), INV 57344 (256), BETA 57600 (256). total 57856
//             v_s aliases 18432 ([128][65] f32 = 33280)
// ---------------------------------------------------------------------------
#define C_AHI 0
#define C_ALO 9216
#define C_XHI 18432
#define C_XLO 35840
#define C_KT  53248
#define C_INV 57344
#define C_BETA 57600
#define C_SMEM 57856

__global__ __launch_bounds__(256,2) void k_fc2kv(
    const float* __restrict__ fc2_w, const float* __restrict__ fc2_bn)
{
    extern __shared__ char sm[];
    __nv_bfloat16* aHi = (__nv_bfloat16*)(sm + C_AHI);
    __nv_bfloat16* aLo = (__nv_bfloat16*)(sm + C_ALO);
    __nv_bfloat16* xHi = (__nv_bfloat16*)(sm + C_XHI);
    __nv_bfloat16* xLo = (__nv_bfloat16*)(sm + C_XLO);
    float* s_K   = (float*)(sm + C_KT);
    float* s_inv = (float*)(sm + C_INV);
    float* s_beta= (float*)(sm + C_BETA);
    float* v_s   = (float*)(sm + C_XHI);   // alias, used after mainloop
    uint32_t sb = smem_u32(sm);

    int tid = threadIdx.x;
    int b  = blockIdx.y;
    int n0 = blockIdx.x * TPX;

    // weights 64x64
    for (int i=tid; i<64*32; i+=256){
        int o = i>>5, c2 = (i&31)<<1;
        uint32_t hi, lo; bsplit2(fc2_w[o*64+c2], fc2_w[o*64+c2+1], hi, lo);
        *(uint32_t*)(aHi + o*WS + c2) = hi;
        *(uint32_t*)(aLo + o*WS + c2) = lo;
    }
    // s tile [64 ch][128 px]
    const float* sp = g_s + (size_t)b*CC*NN + n0;
    for (int i=tid; i<64*64; i+=256){
        int c = i>>6, p2 = (i&63)<<1;
        float2 v = *(const float2*)(sp + (size_t)c*NN + p2);
        uint32_t hi, lo; bsplit2(v.x, v.y, hi, lo);
        *(uint32_t*)(xHi + c*XS + p2) = hi;
        *(uint32_t*)(xLo + c*XS + p2) = lo;
    }
    // K tile [8][128]
    {
        int m = tid >> 5, p = tid & 31;
        ((float4*)s_K)[m*(TPX/4)+p] =
            ((const float4*)(g_K + ((size_t)b*MM + m)*NN + n0))[p];
    }
    if (tid < 64){
        float sc=fc2_bn[0*CC+tid], bi=fc2_bn[1*CC+tid];
        float mn=fc2_bn[2*CC+tid], vr=fc2_bn[3*CC+tid];
        float inv = sc*rsqrtf(vr+1e-5f);
        s_inv[tid]=inv; s_beta[tid]=bi-mn*inv;
    }
    __syncthreads();

    int w = tid >> 5, lane = tid & 31;
    int mt = w & 3, ph = w >> 2;
    int m0 = mt*16, p0 = ph*64;

    float acc[8][4];
    #pragma unroll
    for (int i=0;i<8;i++){ acc[i][0]=acc[i][1]=acc[i][2]=acc[i][3]=0.f; }

    int arow = m0 + (lane & 15), acol8 = (lane>>4)*8;
    int brow = (lane & 7) + 8*((lane>>3)&1), bcol8 = (lane>>4)*8;

    #pragma unroll
    for (int kt=0; kt<4; kt++){
        int k0 = kt*16;
        uint32_t aH[4], aL[4];
        uint32_t aaddr = sb + C_AHI + (uint32_t)(arow*WS + k0 + acol8)*2;
        ldsm4(aH, aaddr);
        ldsm4(aL, aaddr + (C_ALO - C_AHI));
        #pragma unroll
        for (int np=0; np<4; np++){
            uint32_t baddr = sb + C_XHI + (uint32_t)((k0+brow)*XS + p0 + np*16 + bcol8)*2;
            uint32_t bH[4], bL[4];
            ldsm4t(bH, baddr);
            ldsm4t(bL, baddr + (C_XLO - C_XHI));
            mma16816(acc[2*np],   aH, bH);
            mma16816(acc[2*np],   aL, bH);
            mma16816(acc[2*np],   aH, bL);
            mma16816(acc[2*np+1], aH, bH+2);
            mma16816(acc[2*np+1], aL, bH+2);
            mma16816(acc[2*np+1], aH, bL+2);
        }
    }

    // epilogue: xc = relu6(bn(D)); V = g_Vpartial + xc (registers)
    int g = lane >> 2, t2 = (lane & 3)*2;
    int o0 = m0 + g, o1 = o0 + 8;
    float i0 = s_inv[o0], e0 = s_beta[o0], i1 = s_inv[o1], e1 = s_beta[o1];
    float2 v0[8], v1[8];
    {
        const float* vp0 = g_V + ((size_t)b*CC + o0)*NN + n0 + p0 + t2;
        const float* vp1 = g_V + ((size_t)b*CC + o1)*NN + n0 + p0 + t2;
        #pragma unroll
        for (int nt=0; nt<8; nt++){
            float2 a = *(const float2*)(vp0 + nt*8);
            float2 c = *(const float2*)(vp1 + nt*8);
            a.x += relu6f(acc[nt][0]*i0+e0); a.y += relu6f(acc[nt][1]*i0+e0);
            c.x += relu6f(acc[nt][2]*i1+e1); c.y += relu6f(acc[nt][3]*i1+e1);
            v0[nt]=a; v1[nt]=c;
        }
    }
    __syncthreads();   // everyone done reading xHi/xLo -> reuse as v_s

    #pragma unroll
    for (int nt=0; nt<8; nt++){
        int px = p0 + nt*8 + t2;
        v_s[ px   *65 + o0] = v0[nt].x;
        v_s[(px+1)*65 + o0] = v0[nt].y;
        v_s[ px   *65 + o1] = v1[nt].x;
        v_s[(px+1)*65 + o1] = v1[nt].y;
    }
    __syncthreads();

    // KV reduction
    {
        int m = tid >> 6, c = tid & 63;
        const float* k0r = s_K + m*TPX;
        const float* k1r = s_K + (m+4)*TPX;
        float a0=0.f, a1=0.f;
        #pragma unroll 8
        for (int p=0;p<TPX;p++){
            float v = v_s[p*65 + c];
            a0 = fmaf(k0r[p], v, a0);
            a1 = fmaf(k1r[p], v, a1);
        }
        atomicAdd(&g_KV[b*MM*CC + m*CC     + c], a0);
        atomicAdd(&g_KV[b*MM*CC + (m+4)*CC + c], a1);
    }
}

// ---------------------------------------------------------------------------
// K5: out = x + gamma * (Qt . KV) * norm
// ---------------------------------------------------------------------------
__global__ __launch_bounds__(256) void k_out(
    const float* __restrict__ x, const float* __restrict__ gamma,
    float* __restrict__ out)
{
    __shared__ __align__(16) float s_kv[MM*CC];
    __shared__ float s_ks[MM];
    int tid = threadIdx.x;
    int p = blockIdx.x*256 + tid;
    int b = p/NN, n = p%NN;

    for (int i=tid;i<MM*CC;i+=256) s_kv[i] = g_KV[b*MM*CC + i];
    if (tid<MM) s_ks[tid] = g_Ksum[b*MM+tid] + 1e-6f;
    __syncthreads();

    float q[MM];
    #pragma unroll
    for (int m=0;m<MM;m++) q[m] = g_Q[(size_t)b*MM*NN + (size_t)m*NN + n];

    float den=0.f;
    #pragma unroll
    for (int m=0;m<MM;m++) den = fmaf(q[m], s_ks[m], den);
    float gs = gamma[0] / den;

    const float* xb = x + (size_t)b*CC*NN + n;
    float* ob = out + (size_t)b*CC*NN + n;

    const float4* kv4 = (const float4*)s_kv;
    #pragma unroll 4
    for (int c4=0;c4<16;c4++){
        float ax=0.f, ay=0.f, az=0.f, aw=0.f;
        #pragma unroll
        for (int m=0;m<MM;m++){
            float4 w = kv4[m*16+c4];
            ax = fmaf(q[m], w.x, ax); ay = fmaf(q[m], w.y, ay);
            az = fmaf(q[m], w.z, az); aw = fmaf(q[m], w.w, aw);
        }
        int c = 4*c4;
        ob[(size_t)(c+0)*NN] = xb[(size_t)(c+0)*NN] + gs*ax;
        ob[(size_t)(c+1)*NN] = xb[(size_t)(c+1)*NN] + gs*ay;
        ob[(size_t)(c+2)*NN] = xb[(size_t)(c+2)*NN] + gs*az;
        ob[(size_t)(c+3)*NN] = xb[(size_t)(c+3)*NN] + gs*aw;
    }
}

// ---------------------------------------------------------------------------
extern "C" void kernel_launch(void* const* d_in, const int* in_sizes, int n_in,
                              void* d_out, int out_size)
{
    const float* x      = (const float*)d_in[0];
    const float* gamma  = (const float*)d_in[1];
    const float* q_w    = (const float*)d_in[2];
    const float* q_b    = (const float*)d_in[3];
    const float* k_w    = (const float*)d_in[4];
    const float* k_b    = (const float*)d_in[5];
    const float* v_w    = (const float*)d_in[6];
    const float* v_b    = (const float*)d_in[7];
    const float* fc1_w  = (const float*)d_in[8];
    const float* fc1_bn = (const float*)d_in[9];
    const float* c1_w   = (const float*)d_in[10];
    const float* c1_bn  = (const float*)d_in[11];
    const float* c2_w   = (const float*)d_in[12];
    const float* c2_bn  = (const float*)d_in[13];
    const float* fc2_w  = (const float*)d_in[14];
    const float* fc2_bn = (const float*)d_in[15];
    float* out = (float*)d_out;

    cudaFuncSetAttribute(k_front,  cudaFuncAttributeMaxDynamicSharedMemorySize, F_SMEM);
    cudaFuncSetAttribute(k_fc2kv,  cudaFuncAttributeMaxDynamicSharedMemorySize, C_SMEM);

    k_zero<<<8,256>>>();
    k_front<<<dim3(NN/TPX,BB),288,F_SMEM>>>(x,q_w,q_b,k_w,k_b,v_w,v_b,fc1_w,fc1_bn);
    k_dw<<<dim3(WW/32,HH/8,BB*CC),dim3(32,8)>>>(c1_w,c1_bn,c2_w,c2_bn);
    k_fc2kv<<<dim3(NN/TPX,BB),256,C_SMEM>>>(fc2_w,fc2_bn);
    k_out<<<BN/256,256>>>(x,gamma,out);
}

// round 8
// speedup vs baseline: 1.3797x; 1.0992x over previous
#include <cuda_runtime.h>
#include <cuda_bf16.h>
#include <math.h>
#include <stdint.h>

#define BB 4
#define CC 64
#define MM 8
#define HH 224
#define WW 224
#define NN (HH*WW)      // 50176
#define BN (BB*NN)      // 200704
#define TPX 128         // pixels per CTA tile

// Scratch (static device globals — allocation-free per harness rules)
__device__ float g_h[BB*CC*NN];
__device__ float g_s[BB*CC*NN];
__device__ float g_Q[BB*MM*NN];
__device__ float g_K[BB*MM*NN];
__device__ float g_KV[BB*MM*CC];
__device__ float g_Ksum[BB*MM];

__device__ __forceinline__ float relu6f(float x){ return fminf(fmaxf(x,0.f),6.f); }
__device__ __forceinline__ float softplusf(float x){
    return fmaxf(x,0.f) + log1pf(expf(-fabsf(x)));
}
__device__ __forceinline__ uint32_t smem_u32(const void* p){
    uint32_t a;
    asm("{ .reg .u64 t; cvta.to.shared.u64 t, %1; cvt.u32.u64 %0, t; }" : "=r"(a) : "l"(p));
    return a;
}
// split (v0,v1) into packed bf16x2 hi and lo parts (low half = v0)
__device__ __forceinline__ void bsplit2(float v0, float v1, uint32_t& hi, uint32_t& lo){
    __nv_bfloat162 h = __floats2bfloat162_rn(v0, v1);
    float r0 = v0 - __bfloat162float(__low2bfloat16(h));
    float r1 = v1 - __bfloat162float(__high2bfloat16(h));
    __nv_bfloat162 l = __floats2bfloat162_rn(r0, r1);
    hi = *(uint32_t*)&h; lo = *(uint32_t*)&l;
}
__device__ __forceinline__ void ldsm4(uint32_t* r, uint32_t a){
    asm volatile("ldmatrix.sync.aligned.m8n8.x4.shared.b16 {%0,%1,%2,%3}, [%4];"
        : "=r"(r[0]),"=r"(r[1]),"=r"(r[2]),"=r"(r[3]) : "r"(a));
}
__device__ __forceinline__ void ldsm4t(uint32_t* r, uint32_t a){
    asm volatile("ldmatrix.sync.aligned.m8n8.x4.trans.shared.b16 {%0,%1,%2,%3}, [%4];"
        : "=r"(r[0]),"=r"(r[1]),"=r"(r[2]),"=r"(r[3]) : "r"(a));
}
__device__ __forceinline__ void mma16816(float* d, const uint32_t* a, const uint32_t* b){
    asm volatile("mma.sync.aligned.m16n8k16.row.col.f32.bf16.bf16.f32 "
        "{%0,%1,%2,%3}, {%4,%5,%6,%7}, {%8,%9}, {%0,%1,%2,%3};"
        : "+f"(d[0]),"+f"(d[1]),"+f"(d[2]),"+f"(d[3])
        : "r"(a[0]),"r"(a[1]),"r"(a[2]),"r"(a[3]), "r"(b[0]),"r"(b[1]));
}

__global__ void k_zero(){
    int i = blockIdx.x*blockDim.x + threadIdx.x;
    if (i < BB*MM*CC) g_KV[i]   = 0.f;
    if (i < BB*MM)    g_Ksum[i] = 0.f;
}

// ---------------------------------------------------------------------------
// K1 front (mma.sync bf16-split): D[144 out, 128 px] = W[144,64] x Xt[64,128]
// outputs: [v(0..63) | fc1(64..127) | q(128..135) | k(136..143)]
// 288 threads = 9 warps; warp w = m16 tile.
// Fused: KV-partial = K · (v-conv + bias) reduced in-block (no g_V).
// smem bytes:
//   WHI 0 (20736), WLO 20736, XHI 41472 (17408), XLO 58880, consts 76288..77184
//   aliases after mainloop: v_s @0 ([128][65] f32 = 33280), s_Kf @36864 (4096)
// ---------------------------------------------------------------------------
#define F_WHI 0
#define F_WLO 20736
#define F_XHI 41472
#define F_XLO 58880
#define F_CST 76288
#define F_SMEM 77184
#define F_VS   0
#define F_KF   36864
#define WS 72     // weight smem row stride (bf16 elems)
#define XS 136    // x smem row stride (bf16 elems)

__global__ __launch_bounds__(288,2) void k_front(
    const float* __restrict__ x,
    const float* __restrict__ q_w, const float* __restrict__ q_b,
    const float* __restrict__ k_w, const float* __restrict__ k_b,
    const float* __restrict__ v_w, const float* __restrict__ v_b,
    const float* __restrict__ fc1_w, const float* __restrict__ fc1_bn)
{
    extern __shared__ char sm[];
    __nv_bfloat16* wHi = (__nv_bfloat16*)(sm + F_WHI);
    __nv_bfloat16* wLo = (__nv_bfloat16*)(sm + F_WLO);
    __nv_bfloat16* xHi = (__nv_bfloat16*)(sm + F_XHI);
    __nv_bfloat16* xLo = (__nv_bfloat16*)(sm + F_XLO);
    float* s_vb   = (float*)(sm + F_CST);         // 64
    float* s_finv = s_vb + 64;                    // 64
    float* s_fbeta= s_finv + 64;                  // 64
    float* s_qb   = s_fbeta + 64;                 // 8
    float* s_kb   = s_qb + 8;                     // 8
    float* v_s    = (float*)(sm + F_VS);          // alias: [128][65]
    float* s_Kf   = (float*)(sm + F_KF);          // alias: [8][128]
    uint32_t sb = smem_u32(sm);

    int tid = threadIdx.x;
    int b  = blockIdx.y;
    int n0 = blockIdx.x * TPX;

    // weights: 144 x 64, split + pack pairs
    for (int i=tid; i<144*32; i+=288){
        int o = i>>5, c2 = (i&31)<<1;
        const float* src = (o<64) ? v_w + o*64
                         : (o<128)? fc1_w + (o-64)*64
                         : (o<136)? q_w + (o-128)*64
                         :          k_w + (o-136)*64;
        uint32_t hi, lo; bsplit2(src[c2], src[c2+1], hi, lo);
        *(uint32_t*)(wHi + o*WS + c2) = hi;
        *(uint32_t*)(wLo + o*WS + c2) = lo;
    }
    // x tile: [64 ch][128 px]
    const float* xb = x + (size_t)b*CC*NN + n0;
    for (int i=tid; i<64*64; i+=288){
        int c = i>>6, p2 = (i&63)<<1;
        float2 v = *(const float2*)(xb + (size_t)c*NN + p2);
        uint32_t hi, lo; bsplit2(v.x, v.y, hi, lo);
        *(uint32_t*)(xHi + c*XS + p2) = hi;
        *(uint32_t*)(xLo + c*XS + p2) = lo;
    }
    if (tid < 64){
        s_vb[tid] = v_b[tid];
        float sc=fc1_bn[0*CC+tid], bi=fc1_bn[1*CC+tid];
        float mn=fc1_bn[2*CC+tid], vr=fc1_bn[3*CC+tid];
        float inv = sc*rsqrtf(vr+1e-5f);
        s_finv[tid]=inv; s_fbeta[tid]=bi-mn*inv;
    } else if (tid < 72){
        s_qb[tid-64] = q_b[tid-64];
        s_kb[tid-64] = k_b[tid-64];
    }
    __syncthreads();

    int w = tid >> 5, lane = tid & 31;
    int m0 = w*16;

    float acc[16][4];
    #pragma unroll
    for (int i=0;i<16;i++){ acc[i][0]=acc[i][1]=acc[i][2]=acc[i][3]=0.f; }

    int arow = m0 + (lane & 15), acol8 = (lane>>4)*8;
    int brow = (lane & 7) + 8*((lane>>3)&1), bcol8 = (lane>>4)*8;

    #pragma unroll
    for (int kt=0; kt<4; kt++){
        int k0 = kt*16;
        uint32_t aH[4], aL[4];
        uint32_t aaddr = sb + F_WHI + (uint32_t)(arow*WS + k0 + acol8)*2;
        ldsm4(aH, aaddr);
        ldsm4(aL, aaddr + (F_WLO - F_WHI));
        #pragma unroll
        for (int np=0; np<8; np++){
            uint32_t baddr = sb + F_XHI + (uint32_t)((k0+brow)*XS + np*16 + bcol8)*2;
            uint32_t bH[4], bL[4];
            ldsm4t(bH, baddr);
            ldsm4t(bL, baddr + (F_XLO - F_XHI));
            mma16816(acc[2*np],   aH, bH);
            mma16816(acc[2*np],   aL, bH);
            mma16816(acc[2*np],   aH, bL);
            mma16816(acc[2*np+1], aH, bH+2);
            mma16816(acc[2*np+1], aL, bH+2);
            mma16816(acc[2*np+1], aH, bL+2);
        }
    }

    __syncthreads();   // all warps done reading wHi/wLo/xHi/xLo -> safe to alias

    int g = lane >> 2, t2 = (lane & 3)*2;
    if (w < 4){
        // V partial = conv + bias -> smem only
        int o0 = m0 + g, o1 = o0 + 8;
        float b0 = s_vb[o0], b1 = s_vb[o1];
        #pragma unroll
        for (int nt=0; nt<16; nt++){
            int px = nt*8 + t2;
            v_s[ px   *65 + o0] = acc[nt][0]+b0;
            v_s[(px+1)*65 + o0] = acc[nt][1]+b0;
            v_s[ px   *65 + o1] = acc[nt][2]+b1;
            v_s[(px+1)*65 + o1] = acc[nt][3]+b1;
        }
    } else if (w < 8){
        int o0 = m0 - 64 + g, o1 = o0 + 8;
        float i0=s_finv[o0], e0=s_fbeta[o0], i1=s_finv[o1], e1=s_fbeta[o1];
        float* p0 = g_h + ((size_t)b*CC + o0)*NN + n0 + t2;
        float* p1 = g_h + ((size_t)b*CC + o1)*NN + n0 + t2;
        #pragma unroll
        for (int nt=0; nt<16; nt++){
            *(float2*)(p0 + nt*8) = make_float2(relu6f(acc[nt][0]*i0+e0), relu6f(acc[nt][1]*i0+e0));
            *(float2*)(p1 + nt*8) = make_float2(relu6f(acc[nt][2]*i1+e1), relu6f(acc[nt][3]*i1+e1));
        }
    } else {
        // rows g -> Q[m=g], rows g+8 -> K[m=g]
        float bq = s_qb[g], bk = s_kb[g];
        float* pq = g_Q + ((size_t)b*MM + g)*NN + n0 + t2;
        float* pk = g_K + ((size_t)b*MM + g)*NN + n0 + t2;
        float ksum = 0.f;
        #pragma unroll
        for (int nt=0; nt<16; nt++){
            int px = nt*8 + t2;
            float q0 = softplusf(acc[nt][0]+bq), q1 = softplusf(acc[nt][1]+bq);
            float k0v = softplusf(acc[nt][2]+bk), k1v = softplusf(acc[nt][3]+bk);
            *(float2*)(pq + nt*8) = make_float2(q0, q1);
            *(float2*)(pk + nt*8) = make_float2(k0v, k1v);
            s_Kf[g*TPX + px]   = k0v;
            s_Kf[g*TPX + px+1] = k1v;
            ksum += k0v + k1v;
        }
        ksum += __shfl_xor_sync(0xffffffffu, ksum, 1);
        ksum += __shfl_xor_sync(0xffffffffu, ksum, 2);
        if ((lane & 3) == 0) atomicAdd(&g_Ksum[b*MM + g], ksum);
    }
    __syncthreads();

    // KV-partial reduction: KV[b,m,c] += sum_px K[m,px]*Vpart[c,px]
    if (tid < 256){
        int m = tid >> 6, c = tid & 63;
        const float* k0r = s_Kf + m*TPX;
        const float* k1r = s_Kf + (m+4)*TPX;
        float a0=0.f, a1=0.f;
        #pragma unroll 8
        for (int p=0;p<TPX;p++){
            float v = v_s[p*65 + c];
            a0 = fmaf(k0r[p], v, a0);
            a1 = fmaf(k1r[p], v, a1);
        }
        atomicAdd(&g_KV[b*MM*CC + m*CC     + c], a0);
        atomicAdd(&g_KV[b*MM*CC + (m+4)*CC + c], a1);
    }
}

// ---------------------------------------------------------------------------
// K2: depthwise 5x5 + 3x3 (both BN+ReLU6), summed -> g_s
// ---------------------------------------------------------------------------
__global__ __launch_bounds__(256) void k_dw(
    const float* __restrict__ w5, const float* __restrict__ bn5,
    const float* __restrict__ w3, const float* __restrict__ bn3)
{
    int bc = blockIdx.z;
    int c  = bc & (CC-1);
    int y0 = blockIdx.y*8, x0 = blockIdx.x*32;

    __shared__ float t[12][36];
    __shared__ float s_w5[25], s_w3[9], s_c[4];

    int tid = threadIdx.y*32 + threadIdx.x;
    const float* plane = g_h + (size_t)bc*NN;

    for (int i=tid;i<12*36;i+=256){
        int ly=i/36, lx=i%36;
        int gy=y0+ly-2, gx=x0+lx-2;
        float v = 0.f;
        if (gy>=0 && gy<HH && gx>=0 && gx<WW) v = plane[gy*WW+gx];
        t[ly][lx] = v;
    }
    if (tid<25) s_w5[tid] = w5[c*25+tid];
    if (tid<9)  s_w3[tid] = w3[c*9+tid];
    if (tid==0){
        float inv = bn5[0*CC+c]*rsqrtf(bn5[3*CC+c]+1e-5f);
        s_c[0]=inv; s_c[1]=bn5[1*CC+c]-bn5[2*CC+c]*inv;
    }
    if (tid==32){
        float inv = bn3[0*CC+c]*rsqrtf(bn3[3*CC+c]+1e-5f);
        s_c[2]=inv; s_c[3]=bn3[1*CC+c]-bn3[2*CC+c]*inv;
    }
    __syncthreads();

    int ty=threadIdx.y, tx=threadIdx.x;
    float a5=0.f;
    #pragma unroll
    for (int i=0;i<5;i++)
        #pragma unroll
        for (int j=0;j<5;j++)
            a5 = fmaf(s_w5[i*5+j], t[ty+i][tx+j], a5);
    float a3=0.f;
    #pragma unroll
    for (int i=0;i<3;i++)
        #pragma unroll
        for (int j=0;j<3;j++)
            a3 = fmaf(s_w3[i*3+j], t[ty+1+i][tx+1+j], a3);

    float r = relu6f(a5*s_c[0]+s_c[1]) + relu6f(a3*s_c[2]+s_c[3]);
    g_s[(size_t)bc*NN + (y0+ty)*WW + (x0+tx)] = r;
}

// ---------------------------------------------------------------------------
// K3: fc2 (mma.sync bf16-split) + fused KV of xc only.
// D[64 out, 128 px] = W[64,64] x St[64,128]; xc=relu6(bn(D)) -> smem;
// KV[b,m,c] += sum_n K*xc with atomics.  (V-partial contribution added by k_front)
// 256 threads = 8 warps: mt = w&3 (out tile), ph = w>>2 (px half)
// ---------------------------------------------------------------------------
#define C_AHI 0
#define C_ALO 9216
#define C_XHI 18432
#define C_XLO 35840
#define C_KT  53248
#define C_INV 57344
#define C_BETA 57600
#define C_SMEM 57856

__global__ __launch_bounds__(256,3) void k_fc2kv(
    const float* __restrict__ fc2_w, const float* __restrict__ fc2_bn)
{
    extern __shared__ char sm[];
    __nv_bfloat16* aHi = (__nv_bfloat16*)(sm + C_AHI);
    __nv_bfloat16* aLo = (__nv_bfloat16*)(sm + C_ALO);
    __nv_bfloat16* xHi = (__nv_bfloat16*)(sm + C_XHI);
    __nv_bfloat16* xLo = (__nv_bfloat16*)(sm + C_XLO);
    float* s_K   = (float*)(sm + C_KT);
    float* s_inv = (float*)(sm + C_INV);
    float* s_beta= (float*)(sm + C_BETA);
    float* v_s   = (float*)(sm + C_XHI);   // alias, used after mainloop
    uint32_t sb = smem_u32(sm);

    int tid = threadIdx.x;
    int b  = blockIdx.y;
    int n0 = blockIdx.x * TPX;

    // weights 64x64
    for (int i=tid; i<64*32; i+=256){
        int o = i>>5, c2 = (i&31)<<1;
        uint32_t hi, lo; bsplit2(fc2_w[o*64+c2], fc2_w[o*64+c2+1], hi, lo);
        *(uint32_t*)(aHi + o*WS + c2) = hi;
        *(uint32_t*)(aLo + o*WS + c2) = lo;
    }
    // s tile [64 ch][128 px]
    const float* sp = g_s + (size_t)b*CC*NN + n0;
    for (int i=tid; i<64*64; i+=256){
        int c = i>>6, p2 = (i&63)<<1;
        float2 v = *(const float2*)(sp + (size_t)c*NN + p2);
        uint32_t hi, lo; bsplit2(v.x, v.y, hi, lo);
        *(uint32_t*)(xHi + c*XS + p2) = hi;
        *(uint32_t*)(xLo + c*XS + p2) = lo;
    }
    // K tile [8][128]
    {
        int m = tid >> 5, p = tid & 31;
        ((float4*)s_K)[m*(TPX/4)+p] =
            ((const float4*)(g_K + ((size_t)b*MM + m)*NN + n0))[p];
    }
    if (tid < 64){
        float sc=fc2_bn[0*CC+tid], bi=fc2_bn[1*CC+tid];
        float mn=fc2_bn[2*CC+tid], vr=fc2_bn[3*CC+tid];
        float inv = sc*rsqrtf(vr+1e-5f);
        s_inv[tid]=inv; s_beta[tid]=bi-mn*inv;
    }
    __syncthreads();

    int w = tid >> 5, lane = tid & 31;
    int mt = w & 3, ph = w >> 2;
    int m0 = mt*16, p0 = ph*64;

    float acc[8][4];
    #pragma unroll
    for (int i=0;i<8;i++){ acc[i][0]=acc[i][1]=acc[i][2]=acc[i][3]=0.f; }

    int arow = m0 + (lane & 15), acol8 = (lane>>4)*8;
    int brow = (lane & 7) + 8*((lane>>3)&1), bcol8 = (lane>>4)*8;

    #pragma unroll
    for (int kt=0; kt<4; kt++){
        int k0 = kt*16;
        uint32_t aH[4], aL[4];
        uint32_t aaddr = sb + C_AHI + (uint32_t)(arow*WS + k0 + acol8)*2;
        ldsm4(aH, aaddr);
        ldsm4(aL, aaddr + (C_ALO - C_AHI));
        #pragma unroll
        for (int np=0; np<4; np++){
            uint32_t baddr = sb + C_XHI + (uint32_t)((k0+brow)*XS + p0 + np*16 + bcol8)*2;
            uint32_t bH[4], bL[4];
            ldsm4t(bH, baddr);
            ldsm4t(bL, baddr + (C_XLO - C_XHI));
            mma16816(acc[2*np],   aH, bH);
            mma16816(acc[2*np],   aL, bH);
            mma16816(acc[2*np],   aH, bL);
            mma16816(acc[2*np+1], aH, bH+2);
            mma16816(acc[2*np+1], aL, bH+2);
            mma16816(acc[2*np+1], aH, bL+2);
        }
    }

    __syncthreads();   // everyone done reading xHi/xLo -> reuse as v_s

    // epilogue: xc = relu6(bn(D)) -> smem directly
    int g = lane >> 2, t2 = (lane & 3)*2;
    int o0 = m0 + g, o1 = o0 + 8;
    float i0 = s_inv[o0], e0 = s_beta[o0], i1 = s_inv[o1], e1 = s_beta[o1];
    #pragma unroll
    for (int nt=0; nt<8; nt++){
        int px = p0 + nt*8 + t2;
        v_s[ px   *65 + o0] = relu6f(acc[nt][0]*i0+e0);
        v_s[(px+1)*65 + o0] = relu6f(acc[nt][1]*i0+e0);
        v_s[ px   *65 + o1] = relu6f(acc[nt][2]*i1+e1);
        v_s[(px+1)*65 + o1] = relu6f(acc[nt][3]*i1+e1);
    }
    __syncthreads();

    // KV reduction over xc
    {
        int m = tid >> 6, c = tid & 63;
        const float* k0r = s_K + m*TPX;
        const float* k1r = s_K + (m+4)*TPX;
        float a0=0.f, a1=0.f;
        #pragma unroll 8
        for (int p=0;p<TPX;p++){
            float v = v_s[p*65 + c];
            a0 = fmaf(k0r[p], v, a0);
            a1 = fmaf(k1r[p], v, a1);
        }
        atomicAdd(&g_KV[b*MM*CC + m*CC     + c], a0);
        atomicAdd(&g_KV[b*MM*CC + (m+4)*CC + c], a1);
    }
}

// ---------------------------------------------------------------------------
// K5: out = x + gamma * (Qt . KV) * norm
// ---------------------------------------------------------------------------
__global__ __launch_bounds__(256) void k_out(
    const float* __restrict__ x, const float* __restrict__ gamma,
    float* __restrict__ out)
{
    __shared__ __align__(16) float s_kv[MM*CC];
    __shared__ float s_ks[MM];
    int tid = threadIdx.x;
    int p = blockIdx.x*256 + tid;
    int b = p/NN, n = p%NN;

    for (int i=tid;i<MM*CC;i+=256) s_kv[i] = g_KV[b*MM*CC + i];
    if (tid<MM) s_ks[tid] = g_Ksum[b*MM+tid] + 1e-6f;
    __syncthreads();

    float q[MM];
    #pragma unroll
    for (int m=0;m<MM;m++) q[m] = g_Q[(size_t)b*MM*NN + (size_t)m*NN + n];

    float den=0.f;
    #pragma unroll
    for (int m=0;m<MM;m++) den = fmaf(q[m], s_ks[m], den);
    float gs = gamma[0] / den;

    const float* xb = x + (size_t)b*CC*NN + n;
    float* ob = out + (size_t)b*CC*NN + n;

    const float4* kv4 = (const float4*)s_kv;
    #pragma unroll 4
    for (int c4=0;c4<16;c4++){
        float ax=0.f, ay=0.f, az=0.f, aw=0.f;
        #pragma unroll
        for (int m=0;m<MM;m++){
            float4 w = kv4[m*16+c4];
            ax = fmaf(q[m], w.x, ax); ay = fmaf(q[m], w.y, ay);
            az = fmaf(q[m], w.z, az); aw = fmaf(q[m], w.w, aw);
        }
        int c = 4*c4;
        ob[(size_t)(c+0)*NN] = xb[(size_t)(c+0)*NN] + gs*ax;
        ob[(size_t)(c+1)*NN] = xb[(size_t)(c+1)*NN] + gs*ay;
        ob[(size_t)(c+2)*NN] = xb[(size_t)(c+2)*NN] + gs*az;
        ob[(size_t)(c+3)*NN] = xb[(size_t)(c+3)*NN] + gs*aw;
    }
}

// ---------------------------------------------------------------------------
extern "C" void kernel_launch(void* const* d_in, const int* in_sizes, int n_in,
                              void* d_out, int out_size)
{
    const float* x      = (const float*)d_in[0];
    const float* gamma  = (const float*)d_in[1];
    const float* q_w    = (const float*)d_in[2];
    const float* q_b    = (const float*)d_in[3];
    const float* k_w    = (const float*)d_in[4];
    const float* k_b    = (const float*)d_in[5];
    const float* v_w    = (const float*)d_in[6];
    const float* v_b    = (const float*)d_in[7];
    const float* fc1_w  = (const float*)d_in[8];
    const float* fc1_bn = (const float*)d_in[9];
    const float* c1_w   = (const float*)d_in[10];
    const float* c1_bn  = (const float*)d_in[11];
    const float* c2_w   = (const float*)d_in[12];
    const float* c2_bn  = (const float*)d_in[13];
    const float* fc2_w  = (const float*)d_in[14];
    const float* fc2_bn = (const float*)d_in[15];
    float* out = (float*)d_out;

    cudaFuncSetAttribute(k_front,  cudaFuncAttributeMaxDynamicSharedMemorySize, F_SMEM);
    cudaFuncSetAttribute(k_fc2kv,  cudaFuncAttributeMaxDynamicSharedMemorySize, C_SMEM);

    k_zero<<<8,256>>>();
    k_front<<<dim3(NN/TPX,BB),288,F_SMEM>>>(x,q_w,q_b,k_w,k_b,v_w,v_b,fc1_w,fc1_bn);
    k_dw<<<dim3(WW/32,HH/8,BB*CC),dim3(32,8)>>>(c1_w,c1_bn,c2_w,c2_bn);
    k_fc2kv<<<dim3(NN/TPX,BB),256,C_SMEM>>>(fc2_w,fc2_bn);
    k_out<<<BN/256,256>>>(x,gamma,out);
}

// round 9
// speedup vs baseline: 1.6507x; 1.1964x over previous
#include <cuda_runtime.h>
#include <cuda_bf16.h>
#include <cuda_fp16.h>
#include <math.h>
#include <stdint.h>

#define BB 4
#define CC 64
#define MM 8
#define HH 224
#define WW 224
#define NN (HH*WW)      // 50176
#define BN (BB*NN)      // 200704
#define TPX 128         // pixels per CTA tile

// Scratch (static device globals — allocation-free per harness rules)
__device__ __half g_h[BB*CC*NN];
__device__ __half g_s[BB*CC*NN];
__device__ float g_Q[BB*MM*NN];
__device__ float g_K[BB*MM*NN];
__device__ float g_KV[BB*MM*CC];
__device__ float g_Ksum[BB*MM];

__device__ __forceinline__ float relu6f(float x){ return fminf(fmaxf(x,0.f),6.f); }
__device__ __forceinline__ float softplusf(float x){
    return fmaxf(x,0.f) + log1pf(expf(-fabsf(x)));
}
__device__ __forceinline__ uint32_t smem_u32(const void* p){
    uint32_t a;
    asm("{ .reg .u64 t; cvta.to.shared.u64 t, %1; cvt.u32.u64 %0, t; }" : "=r"(a) : "l"(p));
    return a;
}
// split (v0,v1) into packed bf16x2 hi and lo parts (low half = v0)
__device__ __forceinline__ void bsplit2(float v0, float v1, uint32_t& hi, uint32_t& lo){
    __nv_bfloat162 h = __floats2bfloat162_rn(v0, v1);
    float r0 = v0 - __bfloat162float(__low2bfloat16(h));
    float r1 = v1 - __bfloat162float(__high2bfloat16(h));
    __nv_bfloat162 l = __floats2bfloat162_rn(r0, r1);
    hi = *(uint32_t*)&h; lo = *(uint32_t*)&l;
}
__device__ __forceinline__ void ldsm4(uint32_t* r, uint32_t a){
    asm volatile("ldmatrix.sync.aligned.m8n8.x4.shared.b16 {%0,%1,%2,%3}, [%4];"
        : "=r"(r[0]),"=r"(r[1]),"=r"(r[2]),"=r"(r[3]) : "r"(a));
}
__device__ __forceinline__ void ldsm4t(uint32_t* r, uint32_t a){
    asm volatile("ldmatrix.sync.aligned.m8n8.x4.trans.shared.b16 {%0,%1,%2,%3}, [%4];"
        : "=r"(r[0]),"=r"(r[1]),"=r"(r[2]),"=r"(r[3]) : "r"(a));
}
__device__ __forceinline__ void mma16816(float* d, const uint32_t* a, const uint32_t* b){
    asm volatile("mma.sync.aligned.m16n8k16.row.col.f32.bf16.bf16.f32 "
        "{%0,%1,%2,%3}, {%4,%5,%6,%7}, {%8,%9}, {%0,%1,%2,%3};"
        : "+f"(d[0]),"+f"(d[1]),"+f"(d[2]),"+f"(d[3])
        : "r"(a[0]),"r"(a[1]),"r"(a[2]),"r"(a[3]), "r"(b[0]),"r"(b[1]));
}
__device__ __forceinline__ void mma16816h(float* d, const uint32_t* a, const uint32_t* b){
    asm volatile("mma.sync.aligned.m16n8k16.row.col.f32.f16.f16.f32 "
        "{%0,%1,%2,%3}, {%4,%5,%6,%7}, {%8,%9}, {%0,%1,%2,%3};"
        : "+f"(d[0]),"+f"(d[1]),"+f"(d[2]),"+f"(d[3])
        : "r"(a[0]),"r"(a[1]),"r"(a[2]),"r"(a[3]), "r"(b[0]),"r"(b[1]));
}

__global__ void k_zero(){
    int i = blockIdx.x*blockDim.x + threadIdx.x;
    if (i < BB*MM*CC) g_KV[i]   = 0.f;
    if (i < BB*MM)    g_Ksum[i] = 0.f;
}

// ---------------------------------------------------------------------------
// K1 front (mma.sync bf16-split): D[144 out, 128 px] = W[144,64] x Xt[64,128]
// outputs: [v(0..63) | fc1(64..127) | q(128..135) | k(136..143)]
// 288 threads = 9 warps. Fused in-block KV-partial = K · (v-conv + bias).
// h written as fp16.
// ---------------------------------------------------------------------------
#define F_WHI 0
#define F_WLO 20736
#define F_XHI 41472
#define F_XLO 58880
#define F_CST 76288
#define F_SMEM 77184
#define F_VS   0
#define F_KF   36864
#define WS 72     // weight smem row stride (bf16/f16 elems)
#define XS 136    // x smem row stride (bf16/f16 elems)

__global__ __launch_bounds__(288,2) void k_front(
    const float* __restrict__ x,
    const float* __restrict__ q_w, const float* __restrict__ q_b,
    const float* __restrict__ k_w, const float* __restrict__ k_b,
    const float* __restrict__ v_w, const float* __restrict__ v_b,
    const float* __restrict__ fc1_w, const float* __restrict__ fc1_bn)
{
    extern __shared__ char sm[];
    __nv_bfloat16* wHi = (__nv_bfloat16*)(sm + F_WHI);
    __nv_bfloat16* wLo = (__nv_bfloat16*)(sm + F_WLO);
    __nv_bfloat16* xHi = (__nv_bfloat16*)(sm + F_XHI);
    __nv_bfloat16* xLo = (__nv_bfloat16*)(sm + F_XLO);
    float* s_vb   = (float*)(sm + F_CST);         // 64
    float* s_finv = s_vb + 64;                    // 64
    float* s_fbeta= s_finv + 64;                  // 64
    float* s_qb   = s_fbeta + 64;                 // 8
    float* s_kb   = s_qb + 8;                     // 8
    float* v_s    = (float*)(sm + F_VS);          // alias: [128][65]
    float* s_Kf   = (float*)(sm + F_KF);          // alias: [8][128]
    uint32_t sb = smem_u32(sm);

    int tid = threadIdx.x;
    int b  = blockIdx.y;
    int n0 = blockIdx.x * TPX;

    // weights: 144 x 64, split + pack pairs
    for (int i=tid; i<144*32; i+=288){
        int o = i>>5, c2 = (i&31)<<1;
        const float* src = (o<64) ? v_w + o*64
                         : (o<128)? fc1_w + (o-64)*64
                         : (o<136)? q_w + (o-128)*64
                         :          k_w + (o-136)*64;
        uint32_t hi, lo; bsplit2(src[c2], src[c2+1], hi, lo);
        *(uint32_t*)(wHi + o*WS + c2) = hi;
        *(uint32_t*)(wLo + o*WS + c2) = lo;
    }
    // x tile: [64 ch][128 px]
    const float* xb = x + (size_t)b*CC*NN + n0;
    for (int i=tid; i<64*64; i+=288){
        int c = i>>6, p2 = (i&63)<<1;
        float2 v = *(const float2*)(xb + (size_t)c*NN + p2);
        uint32_t hi, lo; bsplit2(v.x, v.y, hi, lo);
        *(uint32_t*)(xHi + c*XS + p2) = hi;
        *(uint32_t*)(xLo + c*XS + p2) = lo;
    }
    if (tid < 64){
        s_vb[tid] = v_b[tid];
        float sc=fc1_bn[0*CC+tid], bi=fc1_bn[1*CC+tid];
        float mn=fc1_bn[2*CC+tid], vr=fc1_bn[3*CC+tid];
        float inv = sc*rsqrtf(vr+1e-5f);
        s_finv[tid]=inv; s_fbeta[tid]=bi-mn*inv;
    } else if (tid < 72){
        s_qb[tid-64] = q_b[tid-64];
        s_kb[tid-64] = k_b[tid-64];
    }
    __syncthreads();

    int w = tid >> 5, lane = tid & 31;
    int m0 = w*16;

    float acc[16][4];
    #pragma unroll
    for (int i=0;i<16;i++){ acc[i][0]=acc[i][1]=acc[i][2]=acc[i][3]=0.f; }

    int arow = m0 + (lane & 15), acol8 = (lane>>4)*8;
    int brow = (lane & 7) + 8*((lane>>3)&1), bcol8 = (lane>>4)*8;

    #pragma unroll
    for (int kt=0; kt<4; kt++){
        int k0 = kt*16;
        uint32_t aH[4], aL[4];
        uint32_t aaddr = sb + F_WHI + (uint32_t)(arow*WS + k0 + acol8)*2;
        ldsm4(aH, aaddr);
        ldsm4(aL, aaddr + (F_WLO - F_WHI));
        #pragma unroll
        for (int np=0; np<8; np++){
            uint32_t baddr = sb + F_XHI + (uint32_t)((k0+brow)*XS + np*16 + bcol8)*2;
            uint32_t bH[4], bL[4];
            ldsm4t(bH, baddr);
            ldsm4t(bL, baddr + (F_XLO - F_XHI));
            mma16816(acc[2*np],   aH, bH);
            mma16816(acc[2*np],   aL, bH);
            mma16816(acc[2*np],   aH, bL);
            mma16816(acc[2*np+1], aH, bH+2);
            mma16816(acc[2*np+1], aL, bH+2);
            mma16816(acc[2*np+1], aH, bL+2);
        }
    }

    __syncthreads();   // all warps done reading smem operands -> safe to alias

    int g = lane >> 2, t2 = (lane & 3)*2;
    if (w < 4){
        // V partial = conv + bias -> smem only
        int o0 = m0 + g, o1 = o0 + 8;
        float b0 = s_vb[o0], b1 = s_vb[o1];
        #pragma unroll
        for (int nt=0; nt<16; nt++){
            int px = nt*8 + t2;
            v_s[ px   *65 + o0] = acc[nt][0]+b0;
            v_s[(px+1)*65 + o0] = acc[nt][1]+b0;
            v_s[ px   *65 + o1] = acc[nt][2]+b1;
            v_s[(px+1)*65 + o1] = acc[nt][3]+b1;
        }
    } else if (w < 8){
        int o0 = m0 - 64 + g, o1 = o0 + 8;
        float i0=s_finv[o0], e0=s_fbeta[o0], i1=s_finv[o1], e1=s_fbeta[o1];
        __half* p0 = g_h + ((size_t)b*CC + o0)*NN + n0 + t2;
        __half* p1 = g_h + ((size_t)b*CC + o1)*NN + n0 + t2;
        #pragma unroll
        for (int nt=0; nt<16; nt++){
            *(half2*)(p0 + nt*8) = __floats2half2_rn(relu6f(acc[nt][0]*i0+e0), relu6f(acc[nt][1]*i0+e0));
            *(half2*)(p1 + nt*8) = __floats2half2_rn(relu6f(acc[nt][2]*i1+e1), relu6f(acc[nt][3]*i1+e1));
        }
    } else {
        // rows g -> Q[m=g], rows g+8 -> K[m=g]
        float bq = s_qb[g], bk = s_kb[g];
        float* pq = g_Q + ((size_t)b*MM + g)*NN + n0 + t2;
        float* pk = g_K + ((size_t)b*MM + g)*NN + n0 + t2;
        float ksum = 0.f;
        #pragma unroll
        for (int nt=0; nt<16; nt++){
            int px = nt*8 + t2;
            float q0 = softplusf(acc[nt][0]+bq), q1 = softplusf(acc[nt][1]+bq);
            float k0v = softplusf(acc[nt][2]+bk), k1v = softplusf(acc[nt][3]+bk);
            *(float2*)(pq + nt*8) = make_float2(q0, q1);
            *(float2*)(pk + nt*8) = make_float2(k0v, k1v);
            s_Kf[g*TPX + px]   = k0v;
            s_Kf[g*TPX + px+1] = k1v;
            ksum += k0v + k1v;
        }
        ksum += __shfl_xor_sync(0xffffffffu, ksum, 1);
        ksum += __shfl_xor_sync(0xffffffffu, ksum, 2);
        if ((lane & 3) == 0) atomicAdd(&g_Ksum[b*MM + g], ksum);
    }
    __syncthreads();

    // KV-partial reduction: KV[b,m,c] += sum_px K[m,px]*Vpart[c,px]
    if (tid < 256){
        int m = tid >> 6, c = tid & 63;
        const float* k0r = s_Kf + m*TPX;
        const float* k1r = s_Kf + (m+4)*TPX;
        float a0=0.f, a1=0.f;
        #pragma unroll 8
        for (int p=0;p<TPX;p++){
            float v = v_s[p*65 + c];
            a0 = fmaf(k0r[p], v, a0);
            a1 = fmaf(k1r[p], v, a1);
        }
        atomicAdd(&g_KV[b*MM*CC + m*CC     + c], a0);
        atomicAdd(&g_KV[b*MM*CC + (m+4)*CC + c], a1);
    }
}

// ---------------------------------------------------------------------------
// K2: depthwise 5x5 + 3x3 (both BN+ReLU6), summed -> g_s (fp16 in/out)
// 32x16 output tile, 2 rows per thread.
// ---------------------------------------------------------------------------
__global__ __launch_bounds__(256) void k_dw(
    const float* __restrict__ w5, const float* __restrict__ bn5,
    const float* __restrict__ w3, const float* __restrict__ bn3)
{
    int bc = blockIdx.z;
    int c  = bc & (CC-1);
    int y0 = blockIdx.y*16, x0 = blockIdx.x*32;

    __shared__ float t[20][36];
    __shared__ float s_w5[25], s_w3[9], s_c[4];

    int tid = threadIdx.y*32 + threadIdx.x;
    const __half* plane = g_h + (size_t)bc*NN;

    for (int i=tid;i<20*36;i+=256){
        int ly=i/36, lx=i%36;
        int gy=y0+ly-2, gx=x0+lx-2;
        float v = 0.f;
        if (gy>=0 && gy<HH && gx>=0 && gx<WW) v = __half2float(plane[gy*WW+gx]);
        t[ly][lx] = v;
    }
    if (tid<25) s_w5[tid] = w5[c*25+tid];
    if (tid<9)  s_w3[tid] = w3[c*9+tid];
    if (tid==0){
        float inv = bn5[0*CC+c]*rsqrtf(bn5[3*CC+c]+1e-5f);
        s_c[0]=inv; s_c[1]=bn5[1*CC+c]-bn5[2*CC+c]*inv;
    }
    if (tid==32){
        float inv = bn3[0*CC+c]*rsqrtf(bn3[3*CC+c]+1e-5f);
        s_c[2]=inv; s_c[3]=bn3[1*CC+c]-bn3[2*CC+c]*inv;
    }
    __syncthreads();

    int ty=threadIdx.y, tx=threadIdx.x;
    float a5a=0.f, a5b=0.f;
    #pragma unroll
    for (int i=0;i<5;i++)
        #pragma unroll
        for (int j=0;j<5;j++){
            float wv = s_w5[i*5+j];
            a5a = fmaf(wv, t[ty+i][tx+j],   a5a);
            a5b = fmaf(wv, t[ty+8+i][tx+j], a5b);
        }
    float a3a=0.f, a3b=0.f;
    #pragma unroll
    for (int i=0;i<3;i++)
        #pragma unroll
        for (int j=0;j<3;j++){
            float wv = s_w3[i*3+j];
            a3a = fmaf(wv, t[ty+1+i][tx+1+j], a3a);
            a3b = fmaf(wv, t[ty+9+i][tx+1+j], a3b);
        }

    float ra = relu6f(a5a*s_c[0]+s_c[1]) + relu6f(a3a*s_c[2]+s_c[3]);
    float rb = relu6f(a5b*s_c[0]+s_c[1]) + relu6f(a3b*s_c[2]+s_c[3]);
    g_s[(size_t)bc*NN + (y0+ty)*WW   + (x0+tx)] = __float2half(ra);
    g_s[(size_t)bc*NN + (y0+ty+8)*WW + (x0+tx)] = __float2half(rb);
}

// ---------------------------------------------------------------------------
// K3: fc2 (fp16 mma.sync, no split) + fused KV of xc only.
// D[64 out, 128 px] = W[64,64] x St[64,128]; xc=relu6(bn(D)) -> smem;
// KV[b,m,c] += sum_n K*xc with atomics.
// 256 threads = 8 warps: mt = w&3 (out tile), ph = w>>2 (px half)
// smem bytes: AH 0 (9216), XH 9216 (17408), v_s alias 0..33280,
//             KT 33280 (4096), INV 37376 (256), BETA 37632 (256) -> 37888
// ---------------------------------------------------------------------------
#define C_AH  0
#define C_XH  9216
#define C_VS  0
#define C_KT  33280
#define C_INV 37376
#define C_BETA 37632
#define C_SMEM 37888

__global__ __launch_bounds__(256,4) void k_fc2kv(
    const float* __restrict__ fc2_w, const float* __restrict__ fc2_bn)
{
    extern __shared__ char sm[];
    __half* aH = (__half*)(sm + C_AH);
    __half* xH = (__half*)(sm + C_XH);
    float* s_K   = (float*)(sm + C_KT);
    float* s_inv = (float*)(sm + C_INV);
    float* s_beta= (float*)(sm + C_BETA);
    float* v_s   = (float*)(sm + C_VS);   // alias, used after mainloop
    uint32_t sb = smem_u32(sm);

    int tid = threadIdx.x;
    int b  = blockIdx.y;
    int n0 = blockIdx.x * TPX;

    // weights 64x64 -> fp16
    for (int i=tid; i<64*32; i+=256){
        int o = i>>5, c2 = (i&31)<<1;
        *(half2*)(aH + o*WS + c2) = __floats2half2_rn(fc2_w[o*64+c2], fc2_w[o*64+c2+1]);
    }
    // s tile [64 ch][128 px] — raw fp16 copy (16B per op)
    const __half* sp = g_s + (size_t)b*CC*NN + n0;
    for (int i=tid; i<64*16; i+=256){
        int c = i>>4, p8 = (i&15)<<3;
        *(uint4*)(xH + c*XS + p8) = *(const uint4*)(sp + (size_t)c*NN + p8);
    }
    // K tile [8][128]
    {
        int m = tid >> 5, p = tid & 31;
        ((float4*)s_K)[m*(TPX/4)+p] =
            ((const float4*)(g_K + ((size_t)b*MM + m)*NN + n0))[p];
    }
    if (tid < 64){
        float sc=fc2_bn[0*CC+tid], bi=fc2_bn[1*CC+tid];
        float mn=fc2_bn[2*CC+tid], vr=fc2_bn[3*CC+tid];
        float inv = sc*rsqrtf(vr+1e-5f);
        s_inv[tid]=inv; s_beta[tid]=bi-mn*inv;
    }
    __syncthreads();

    int w = tid >> 5, lane = tid & 31;
    int mt = w & 3, ph = w >> 2;
    int m0 = mt*16, p0 = ph*64;

    float acc[8][4];
    #pragma unroll
    for (int i=0;i<8;i++){ acc[i][0]=acc[i][1]=acc[i][2]=acc[i][3]=0.f; }

    int arow = m0 + (lane & 15), acol8 = (lane>>4)*8;
    int brow = (lane & 7) + 8*((lane>>3)&1), bcol8 = (lane>>4)*8;

    #pragma unroll
    for (int kt=0; kt<4; kt++){
        int k0 = kt*16;
        uint32_t a[4];
        ldsm4(a, sb + C_AH + (uint32_t)(arow*WS + k0 + acol8)*2);
        #pragma unroll
        for (int np=0; np<4; np++){
            uint32_t bF[4];
            ldsm4t(bF, sb + C_XH + (uint32_t)((k0+brow)*XS + p0 + np*16 + bcol8)*2);
            mma16816h(acc[2*np],   a, bF);
            mma16816h(acc[2*np+1], a, bF+2);
        }
    }

    __syncthreads();   // everyone done reading xH -> reuse as v_s

    // epilogue: xc = relu6(bn(D)) -> smem directly
    int g = lane >> 2, t2 = (lane & 3)*2;
    int o0 = m0 + g, o1 = o0 + 8;
    float i0 = s_inv[o0], e0 = s_beta[o0], i1 = s_inv[o1], e1 = s_beta[o1];
    #pragma unroll
    for (int nt=0; nt<8; nt++){
        int px = p0 + nt*8 + t2;
        v_s[ px   *65 + o0] = relu6f(acc[nt][0]*i0+e0);
        v_s[(px+1)*65 + o0] = relu6f(acc[nt][1]*i0+e0);
        v_s[ px   *65 + o1] = relu6f(acc[nt][2]*i1+e1);
        v_s[(px+1)*65 + o1] = relu6f(acc[nt][3]*i1+e1);
    }
    __syncthreads();

    // KV reduction over xc
    {
        int m = tid >> 6, c = tid & 63;
        const float* k0r = s_K + m*TPX;
        const float* k1r = s_K + (m+4)*TPX;
        float a0=0.f, a1=0.f;
        #pragma unroll 8
        for (int p=0;p<TPX;p++){
            float v = v_s[p*65 + c];
            a0 = fmaf(k0r[p], v, a0);
            a1 = fmaf(k1r[p], v, a1);
        }
        atomicAdd(&g_KV[b*MM*CC + m*CC     + c], a0);
        atomicAdd(&g_KV[b*MM*CC + (m+4)*CC + c], a1);
    }
}

// ---------------------------------------------------------------------------
// K5: out = x + gamma * (Qt . KV) * norm
// ---------------------------------------------------------------------------
__global__ __launch_bounds__(256) void k_out(
    const float* __restrict__ x, const float* __restrict__ gamma,
    float* __restrict__ out)
{
    __shared__ __align__(16) float s_kv[MM*CC];
    __shared__ float s_ks[MM];
    int tid = threadIdx.x;
    int p = blockIdx.x*256 + tid;
    int b = p/NN, n = p%NN;

    for (int i=tid;i<MM*CC;i+=256) s_kv[i] = g_KV[b*MM*CC + i];
    if (tid<MM) s_ks[tid] = g_Ksum[b*MM+tid] + 1e-6f;
    __syncthreads();

    float q[MM];
    #pragma unroll
    for (int m=0;m<MM;m++) q[m] = g_Q[(size_t)b*MM*NN + (size_t)m*NN + n];

    float den=0.f;
    #pragma unroll
    for (int m=0;m<MM;m++) den = fmaf(q[m], s_ks[m], den);
    float gs = gamma[0] / den;

    const float* xb = x + (size_t)b*CC*NN + n;
    float* ob = out + (size_t)b*CC*NN + n;

    const float4* kv4 = (const float4*)s_kv;
    #pragma unroll 4
    for (int c4=0;c4<16;c4++){
        float ax=0.f, ay=0.f, az=0.f, aw=0.f;
        #pragma unroll
        for (int m=0;m<MM;m++){
            float4 w = kv4[m*16+c4];
            ax = fmaf(q[m], w.x, ax); ay = fmaf(q[m], w.y, ay);
            az = fmaf(q[m], w.z, az); aw = fmaf(q[m], w.w, aw);
        }
        int c = 4*c4;
        ob[(size_t)(c+0)*NN] = xb[(size_t)(c+0)*NN] + gs*ax;
        ob[(size_t)(c+1)*NN] = xb[(size_t)(c+1)*NN] + gs*ay;
        ob[(size_t)(c+2)*NN] = xb[(size_t)(c+2)*NN] + gs*az;
        ob[(size_t)(c+3)*NN] = xb[(size_t)(c+3)*NN] + gs*aw;
    }
}

// ---------------------------------------------------------------------------
extern "C" void kernel_launch(void* const* d_in, const int* in_sizes, int n_in,
                              void* d_out, int out_size)
{
    const float* x      = (const float*)d_in[0];
    const float* gamma  = (const float*)d_in[1];
    const float* q_w    = (const float*)d_in[2];
    const float* q_b    = (const float*)d_in[3];
    const float* k_w    = (const float*)d_in[4];
    const float* k_b    = (const float*)d_in[5];
    const float* v_w    = (const float*)d_in[6];
    const float* v_b    = (const float*)d_in[7];
    const float* fc1_w  = (const float*)d_in[8];
    const float* fc1_bn = (const float*)d_in[9];
    const float* c1_w   = (const float*)d_in[10];
    const float* c1_bn  = (const float*)d_in[11];
    const float* c2_w   = (const float*)d_in[12];
    const float* c2_bn  = (const float*)d_in[13];
    const float* fc2_w  = (const float*)d_in[14];
    const float* fc2_bn = (const float*)d_in[15];
    float* out = (float*)d_out;

    cudaFuncSetAttribute(k_front,  cudaFuncAttributeMaxDynamicSharedMemorySize, F_SMEM);
    cudaFuncSetAttribute(k_fc2kv,  cudaFuncAttributeMaxDynamicSharedMemorySize, C_SMEM);

    k_zero<<<8,256>>>();
    k_front<<<dim3(NN/TPX,BB),288,F_SMEM>>>(x,q_w,q_b,k_w,k_b,v_w,v_b,fc1_w,fc1_bn);
    k_dw<<<dim3(WW/32,HH/16,BB*CC),dim3(32,8)>>>(c1_w,c1_bn,c2_w,c2_bn);
    k_fc2kv<<<dim3(NN/TPX,BB),256,C_SMEM>>>(fc2_w,fc2_bn);
    k_out<<<BN/256,256>>>(x,gamma,out);
}

// round 10
// speedup vs baseline: 1.7895x; 1.0841x over previous
#include <cuda_runtime.h>
#include <cuda_fp16.h>
#include <math.h>
#include <stdint.h>

#define BB 4
#define CC 64
#define MM 8
#define HH 224
#define WW 224
#define NN (HH*WW)      // 50176
#define BN (BB*NN)      // 200704
#define TPX 128         // pixels per CTA tile

// Scratch (static device globals — allocation-free per harness rules)
__device__ __half g_h[BB*CC*NN];
__device__ __half g_s[BB*CC*NN];
__device__ float g_Q[BB*MM*NN];
__device__ float g_K[BB*MM*NN];
__device__ float g_KV[BB*MM*CC];
__device__ float g_Ksum[BB*MM];

__device__ __forceinline__ float relu6f(float x){ return fminf(fmaxf(x,0.f),6.f); }
__device__ __forceinline__ float softplusf(float x){
    return fmaxf(x,0.f) + log1pf(expf(-fabsf(x)));
}
__device__ __forceinline__ uint32_t smem_u32(const void* p){
    uint32_t a;
    asm("{ .reg .u64 t; cvta.to.shared.u64 t, %1; cvt.u32.u64 %0, t; }" : "=r"(a) : "l"(p));
    return a;
}
__device__ __forceinline__ void ldsm4(uint32_t* r, uint32_t a){
    asm volatile("ldmatrix.sync.aligned.m8n8.x4.shared.b16 {%0,%1,%2,%3}, [%4];"
        : "=r"(r[0]),"=r"(r[1]),"=r"(r[2]),"=r"(r[3]) : "r"(a));
}
__device__ __forceinline__ void ldsm4t(uint32_t* r, uint32_t a){
    asm volatile("ldmatrix.sync.aligned.m8n8.x4.trans.shared.b16 {%0,%1,%2,%3}, [%4];"
        : "=r"(r[0]),"=r"(r[1]),"=r"(r[2]),"=r"(r[3]) : "r"(a));
}
__device__ __forceinline__ void mma16816h(float* d, const uint32_t* a, const uint32_t* b){
    asm volatile("mma.sync.aligned.m16n8k16.row.col.f32.f16.f16.f32 "
        "{%0,%1,%2,%3}, {%4,%5,%6,%7}, {%8,%9}, {%0,%1,%2,%3};"
        : "+f"(d[0]),"+f"(d[1]),"+f"(d[2]),"+f"(d[3])
        : "r"(a[0]),"r"(a[1]),"r"(a[2]),"r"(a[3]), "r"(b[0]),"r"(b[1]));
}

__global__ void k_zero(){
    int i = blockIdx.x*blockDim.x + threadIdx.x;
    if (i < BB*MM*CC) g_KV[i]   = 0.f;
    if (i < BB*MM)    g_Ksum[i] = 0.f;
}

// ---------------------------------------------------------------------------
// K1 front (fp16 mma.sync): D[144 out, 128 px] = W[144,64] x Xt[64,128]
// outputs: [v(0..63) | fc1(64..127) | q(128..135) | k(136..143)]
// 288 threads = 9 warps. Fused in-block KV-partial = K · (v-conv + bias).
// smem bytes: WH 0 (20736), XH 20736 (17408), consts @38144 (832) -> 38976
// aliases after mainloop: v_s @0 ([128][65] f32 = 33280), s_Kf @33280 (4096)
// ---------------------------------------------------------------------------
#define F_WH  0
#define F_XH  20736
#define F_CST 38144
#define F_SMEM 38976
#define F_VS   0
#define F_KF   33280
#define WS 72     // weight smem row stride (f16 elems)
#define XS 136    // x smem row stride (f16 elems)

__global__ __launch_bounds__(288,2) void k_front(
    const float* __restrict__ x,
    const float* __restrict__ q_w, const float* __restrict__ q_b,
    const float* __restrict__ k_w, const float* __restrict__ k_b,
    const float* __restrict__ v_w, const float* __restrict__ v_b,
    const float* __restrict__ fc1_w, const float* __restrict__ fc1_bn)
{
    extern __shared__ char sm[];
    __half* wH = (__half*)(sm + F_WH);
    __half* xH = (__half*)(sm + F_XH);
    float* s_vb   = (float*)(sm + F_CST);         // 64
    float* s_finv = s_vb + 64;                    // 64
    float* s_fbeta= s_finv + 64;                  // 64
    float* s_qb   = s_fbeta + 64;                 // 8
    float* s_kb   = s_qb + 8;                     // 8
    float* v_s    = (float*)(sm + F_VS);          // alias: [128][65]
    float* s_Kf   = (float*)(sm + F_KF);          // alias: [8][128]
    uint32_t sb = smem_u32(sm);

    int tid = threadIdx.x;
    int b  = blockIdx.y;
    int n0 = blockIdx.x * TPX;

    // weights: 144 x 64 -> fp16
    for (int i=tid; i<144*32; i+=288){
        int o = i>>5, c2 = (i&31)<<1;
        const float* src = (o<64) ? v_w + o*64
                         : (o<128)? fc1_w + (o-64)*64
                         : (o<136)? q_w + (o-128)*64
                         :          k_w + (o-136)*64;
        *(half2*)(wH + o*WS + c2) = __floats2half2_rn(src[c2], src[c2+1]);
    }
    // x tile: [64 ch][128 px] -> fp16
    const float* xb = x + (size_t)b*CC*NN + n0;
    for (int i=tid; i<64*64; i+=288){
        int c = i>>6, p2 = (i&63)<<1;
        float2 v = *(const float2*)(xb + (size_t)c*NN + p2);
        *(half2*)(xH + c*XS + p2) = __floats2half2_rn(v.x, v.y);
    }
    if (tid < 64){
        s_vb[tid] = v_b[tid];
        float sc=fc1_bn[0*CC+tid], bi=fc1_bn[1*CC+tid];
        float mn=fc1_bn[2*CC+tid], vr=fc1_bn[3*CC+tid];
        float inv = sc*rsqrtf(vr+1e-5f);
        s_finv[tid]=inv; s_fbeta[tid]=bi-mn*inv;
    } else if (tid < 72){
        s_qb[tid-64] = q_b[tid-64];
        s_kb[tid-64] = k_b[tid-64];
    }
    __syncthreads();

    int w = tid >> 5, lane = tid & 31;
    int m0 = w*16;

    float acc[16][4];
    #pragma unroll
    for (int i=0;i<16;i++){ acc[i][0]=acc[i][1]=acc[i][2]=acc[i][3]=0.f; }

    int arow = m0 + (lane & 15), acol8 = (lane>>4)*8;
    int brow = (lane & 7) + 8*((lane>>3)&1), bcol8 = (lane>>4)*8;

    #pragma unroll
    for (int kt=0; kt<4; kt++){
        int k0 = kt*16;
        uint32_t a[4];
        ldsm4(a, sb + F_WH + (uint32_t)(arow*WS + k0 + acol8)*2);
        #pragma unroll
        for (int np=0; np<8; np++){
            uint32_t bF[4];
            ldsm4t(bF, sb + F_XH + (uint32_t)((k0+brow)*XS + np*16 + bcol8)*2);
            mma16816h(acc[2*np],   a, bF);
            mma16816h(acc[2*np+1], a, bF+2);
        }
    }

    __syncthreads();   // all warps done reading smem operands -> safe to alias

    int g = lane >> 2, t2 = (lane & 3)*2;
    if (w < 4){
        // V partial = conv + bias -> smem only
        int o0 = m0 + g, o1 = o0 + 8;
        float b0 = s_vb[o0], b1 = s_vb[o1];
        #pragma unroll
        for (int nt=0; nt<16; nt++){
            int px = nt*8 + t2;
            v_s[ px   *65 + o0] = acc[nt][0]+b0;
            v_s[(px+1)*65 + o0] = acc[nt][1]+b0;
            v_s[ px   *65 + o1] = acc[nt][2]+b1;
            v_s[(px+1)*65 + o1] = acc[nt][3]+b1;
        }
    } else if (w < 8){
        int o0 = m0 - 64 + g, o1 = o0 + 8;
        float i0=s_finv[o0], e0=s_fbeta[o0], i1=s_finv[o1], e1=s_fbeta[o1];
        __half* p0 = g_h + ((size_t)b*CC + o0)*NN + n0 + t2;
        __half* p1 = g_h + ((size_t)b*CC + o1)*NN + n0 + t2;
        #pragma unroll
        for (int nt=0; nt<16; nt++){
            *(half2*)(p0 + nt*8) = __floats2half2_rn(relu6f(acc[nt][0]*i0+e0), relu6f(acc[nt][1]*i0+e0));
            *(half2*)(p1 + nt*8) = __floats2half2_rn(relu6f(acc[nt][2]*i1+e1), relu6f(acc[nt][3]*i1+e1));
        }
    } else {
        // rows g -> Q[m=g], rows g+8 -> K[m=g]
        float bq = s_qb[g], bk = s_kb[g];
        float* pq = g_Q + ((size_t)b*MM + g)*NN + n0 + t2;
        float* pk = g_K + ((size_t)b*MM + g)*NN + n0 + t2;
        float ksum = 0.f;
        #pragma unroll
        for (int nt=0; nt<16; nt++){
            int px = nt*8 + t2;
            float q0 = softplusf(acc[nt][0]+bq), q1 = softplusf(acc[nt][1]+bq);
            float k0v = softplusf(acc[nt][2]+bk), k1v = softplusf(acc[nt][3]+bk);
            *(float2*)(pq + nt*8) = make_float2(q0, q1);
            *(float2*)(pk + nt*8) = make_float2(k0v, k1v);
            s_Kf[g*TPX + px]   = k0v;
            s_Kf[g*TPX + px+1] = k1v;
            ksum += k0v + k1v;
        }
        ksum += __shfl_xor_sync(0xffffffffu, ksum, 1);
        ksum += __shfl_xor_sync(0xffffffffu, ksum, 2);
        if ((lane & 3) == 0) atomicAdd(&g_Ksum[b*MM + g], ksum);
    }
    __syncthreads();

    // KV-partial reduction: KV[b,m,c] += sum_px K[m,px]*Vpart[c,px]
    if (tid < 256){
        int m = tid >> 6, c = tid & 63;
        const float* k0r = s_Kf + m*TPX;
        const float* k1r = s_Kf + (m+4)*TPX;
        float a0=0.f, a1=0.f;
        #pragma unroll 8
        for (int p=0;p<TPX;p++){
            float v = v_s[p*65 + c];
            a0 = fmaf(k0r[p], v, a0);
            a1 = fmaf(k1r[p], v, a1);
        }
        atomicAdd(&g_KV[b*MM*CC + m*CC     + c], a0);
        atomicAdd(&g_KV[b*MM*CC + (m+4)*CC + c], a1);
    }
}

// ---------------------------------------------------------------------------
// K2: depthwise 5x5 + 3x3 (both BN+ReLU6), summed -> g_s (fp16 in/out)
// Block (16,16); tile 32 wide x 16 rows; each thread 2 horizontal px.
// Register column-window: 42 LDS per 2 px.
// ---------------------------------------------------------------------------
__global__ __launch_bounds__(256) void k_dw(
    const float* __restrict__ w5, const float* __restrict__ bn5,
    const float* __restrict__ w3, const float* __restrict__ bn3)
{
    int bc = blockIdx.z;
    int c  = bc & (CC-1);
    int y0 = blockIdx.y*16, x0 = blockIdx.x*32;

    __shared__ float t[20][36];
    __shared__ float s_w5[25], s_w3[9], s_c[4];

    int tid = threadIdx.y*16 + threadIdx.x;
    const __half* plane = g_h + (size_t)bc*NN;

    for (int i=tid;i<20*36;i+=256){
        int ly=i/36, lx=i%36;
        int gy=y0+ly-2, gx=x0+lx-2;
        float v = 0.f;
        if (gy>=0 && gy<HH && gx>=0 && gx<WW) v = __half2float(plane[gy*WW+gx]);
        t[ly][lx] = v;
    }
    if (tid<25) s_w5[tid] = w5[c*25+tid];
    if (tid<9)  s_w3[tid] = w3[c*9+tid];
    if (tid==0){
        float inv = bn5[0*CC+c]*rsqrtf(bn5[3*CC+c]+1e-5f);
        s_c[0]=inv; s_c[1]=bn5[1*CC+c]-bn5[2*CC+c]*inv;
    }
    if (tid==32){
        float inv = bn3[0*CC+c]*rsqrtf(bn3[3*CC+c]+1e-5f);
        s_c[2]=inv; s_c[3]=bn3[1*CC+c]-bn3[2*CC+c]*inv;
    }
    __syncthreads();

    int ty = threadIdx.y;        // 0..15 (row)
    int tx2 = threadIdx.x*2;     // 0,2,..,30 (2 px per thread)

    float a5a=0.f, a5b=0.f;
    #pragma unroll
    for (int i=0;i<5;i++){
        const float* r = &t[ty+i][tx2];
        float c0=r[0], c1=r[1], c2=r[2], c3=r[3], c4=r[4], c5=r[5];
        float w0=s_w5[i*5], w1=s_w5[i*5+1], w2=s_w5[i*5+2], w3v=s_w5[i*5+3], w4=s_w5[i*5+4];
        a5a = fmaf(w0,c0, fmaf(w1,c1, fmaf(w2,c2, fmaf(w3v,c3, fmaf(w4,c4, a5a)))));
        a5b = fmaf(w0,c1, fmaf(w1,c2, fmaf(w2,c3, fmaf(w3v,c4, fmaf(w4,c5, a5b)))));
    }
    float a3a=0.f, a3b=0.f;
    #pragma unroll
    for (int i=0;i<3;i++){
        const float* r = &t[ty+1+i][tx2+1];
        float c0=r[0], c1=r[1], c2=r[2], c3=r[3];
        float w0=s_w3[i*3], w1=s_w3[i*3+1], w2=s_w3[i*3+2];
        a3a = fmaf(w0,c0, fmaf(w1,c1, fmaf(w2,c2, a3a)));
        a3b = fmaf(w0,c1, fmaf(w1,c2, fmaf(w2,c3, a3b)));
    }

    float ra = relu6f(a5a*s_c[0]+s_c[1]) + relu6f(a3a*s_c[2]+s_c[3]);
    float rb = relu6f(a5b*s_c[0]+s_c[1]) + relu6f(a3b*s_c[2]+s_c[3]);
    *(half2*)(g_s + (size_t)bc*NN + (y0+ty)*WW + (x0+tx2)) = __floats2half2_rn(ra, rb);
}

// ---------------------------------------------------------------------------
// K3: fc2 (fp16 mma.sync) + fused KV of xc only. (unchanged from R9)
// ---------------------------------------------------------------------------
#define C_AH  0
#define C_XH  9216
#define C_VS  0
#define C_KT  33280
#define C_INV 37376
#define C_BETA 37632
#define C_SMEM 37888

__global__ __launch_bounds__(256,4) void k_fc2kv(
    const float* __restrict__ fc2_w, const float* __restrict__ fc2_bn)
{
    extern __shared__ char sm[];
    __half* aH = (__half*)(sm + C_AH);
    __half* xH = (__half*)(sm + C_XH);
    float* s_K   = (float*)(sm + C_KT);
    float* s_inv = (float*)(sm + C_INV);
    float* s_beta= (float*)(sm + C_BETA);
    float* v_s   = (float*)(sm + C_VS);   // alias, used after mainloop
    uint32_t sb = smem_u32(sm);

    int tid = threadIdx.x;
    int b  = blockIdx.y;
    int n0 = blockIdx.x * TPX;

    // weights 64x64 -> fp16
    for (int i=tid; i<64*32; i+=256){
        int o = i>>5, c2 = (i&31)<<1;
        *(half2*)(aH + o*WS + c2) = __floats2half2_rn(fc2_w[o*64+c2], fc2_w[o*64+c2+1]);
    }
    // s tile [64 ch][128 px] — raw fp16 copy
    const __half* sp = g_s + (size_t)b*CC*NN + n0;
    for (int i=tid; i<64*16; i+=256){
        int c = i>>4, p8 = (i&15)<<3;
        *(uint4*)(xH + c*XS + p8) = *(const uint4*)(sp + (size_t)c*NN + p8);
    }
    // K tile [8][128]
    {
        int m = tid >> 5, p = tid & 31;
        ((float4*)s_K)[m*(TPX/4)+p] =
            ((const float4*)(g_K + ((size_t)b*MM + m)*NN + n0))[p];
    }
    if (tid < 64){
        float sc=fc2_bn[0*CC+tid], bi=fc2_bn[1*CC+tid];
        float mn=fc2_bn[2*CC+tid], vr=fc2_bn[3*CC+tid];
        float inv = sc*rsqrtf(vr+1e-5f);
        s_inv[tid]=inv; s_beta[tid]=bi-mn*inv;
    }
    __syncthreads();

    int w = tid >> 5, lane = tid & 31;
    int mt = w & 3, ph = w >> 2;
    int m0 = mt*16, p0 = ph*64;

    float acc[8][4];
    #pragma unroll
    for (int i=0;i<8;i++){ acc[i][0]=acc[i][1]=acc[i][2]=acc[i][3]=0.f; }

    int arow = m0 + (lane & 15), acol8 = (lane>>4)*8;
    int brow = (lane & 7) + 8*((lane>>3)&1), bcol8 = (lane>>4)*8;

    #pragma unroll
    for (int kt=0; kt<4; kt++){
        int k0 = kt*16;
        uint32_t a[4];
        ldsm4(a, sb + C_AH + (uint32_t)(arow*WS + k0 + acol8)*2);
        #pragma unroll
        for (int np=0; np<4; np++){
            uint32_t bF[4];
            ldsm4t(bF, sb + C_XH + (uint32_t)((k0+brow)*XS + p0 + np*16 + bcol8)*2);
            mma16816h(acc[2*np],   a, bF);
            mma16816h(acc[2*np+1], a, bF+2);
        }
    }

    __syncthreads();   // everyone done reading xH -> reuse as v_s

    // epilogue: xc = relu6(bn(D)) -> smem directly
    int g = lane >> 2, t2 = (lane & 3)*2;
    int o0 = m0 + g, o1 = o0 + 8;
    float i0 = s_inv[o0], e0 = s_beta[o0], i1 = s_inv[o1], e1 = s_beta[o1];
    #pragma unroll
    for (int nt=0; nt<8; nt++){
        int px = p0 + nt*8 + t2;
        v_s[ px   *65 + o0] = relu6f(acc[nt][0]*i0+e0);
        v_s[(px+1)*65 + o0] = relu6f(acc[nt][1]*i0+e0);
        v_s[ px   *65 + o1] = relu6f(acc[nt][2]*i1+e1);
        v_s[(px+1)*65 + o1] = relu6f(acc[nt][3]*i1+e1);
    }
    __syncthreads();

    // KV reduction over xc
    {
        int m = tid >> 6, c = tid & 63;
        const float* k0r = s_K + m*TPX;
        const float* k1r = s_K + (m+4)*TPX;
        float a0=0.f, a1=0.f;
        #pragma unroll 8
        for (int p=0;p<TPX;p++){
            float v = v_s[p*65 + c];
            a0 = fmaf(k0r[p], v, a0);
            a1 = fmaf(k1r[p], v, a1);
        }
        atomicAdd(&g_KV[b*MM*CC + m*CC     + c], a0);
        atomicAdd(&g_KV[b*MM*CC + (m+4)*CC + c], a1);
    }
}

// ---------------------------------------------------------------------------
// K5: out = x + gamma * (Qt . KV) * norm.  4 pixels per thread (float4).
// ---------------------------------------------------------------------------
__global__ __launch_bounds__(256) void k_out(
    const float* __restrict__ x, const float* __restrict__ gamma,
    float* __restrict__ out)
{
    __shared__ __align__(16) float s_kv[MM*CC];
    __shared__ float s_ks[MM];
    int tid = threadIdx.x;
    int p4 = (blockIdx.x*256 + tid)*4;
    int b = p4/NN, n = p4%NN;   // NN % 1024 == 0 -> b block-uniform

    for (int i=tid;i<MM*CC;i+=256) s_kv[i] = g_KV[b*MM*CC + i];
    if (tid<MM) s_ks[tid] = g_Ksum[b*MM+tid] + 1e-6f;
    __syncthreads();

    float4 q[MM];
    #pragma unroll
    for (int m=0;m<MM;m++)
        q[m] = *(const float4*)(g_Q + (size_t)b*MM*NN + (size_t)m*NN + n);

    float4 den = make_float4(0.f,0.f,0.f,0.f);
    #pragma unroll
    for (int m=0;m<MM;m++){
        float ks = s_ks[m];
        den.x = fmaf(q[m].x, ks, den.x); den.y = fmaf(q[m].y, ks, den.y);
        den.z = fmaf(q[m].z, ks, den.z); den.w = fmaf(q[m].w, ks, den.w);
    }
    float gm = gamma[0];
    float4 gs = make_float4(gm/den.x, gm/den.y, gm/den.z, gm/den.w);

    const float* xb = x + (size_t)b*CC*NN + n;
    float* ob = out + (size_t)b*CC*NN + n;

    #pragma unroll 4
    for (int c=0;c<CC;c++){
        float ax=0.f, ay=0.f, az=0.f, aw=0.f;
        #pragma unroll
        for (int m=0;m<MM;m++){
            float w = s_kv[m*CC + c];
            ax = fmaf(q[m].x, w, ax); ay = fmaf(q[m].y, w, ay);
            az = fmaf(q[m].z, w, az); aw = fmaf(q[m].w, w, aw);
        }
        float4 xv = *(const float4*)(xb + (size_t)c*NN);
        xv.x = fmaf(gs.x, ax, xv.x); xv.y = fmaf(gs.y, ay, xv.y);
        xv.z = fmaf(gs.z, az, xv.z); xv.w = fmaf(gs.w, aw, xv.w);
        *(float4*)(ob + (size_t)c*NN) = xv;
    }
}

// ---------------------------------------------------------------------------
extern "C" void kernel_launch(void* const* d_in, const int* in_sizes, int n_in,
                              void* d_out, int out_size)
{
    const float* x      = (const float*)d_in[0];
    const float* gamma  = (const float*)d_in[1];
    const float* q_w    = (const float*)d_in[2];
    const float* q_b    = (const float*)d_in[3];
    const float* k_w    = (const float*)d_in[4];
    const float* k_b    = (const float*)d_in[5];
    const float* v_w    = (const float*)d_in[6];
    const float* v_b    = (const float*)d_in[7];
    const float* fc1_w  = (const float*)d_in[8];
    const float* fc1_bn = (const float*)d_in[9];
    const float* c1_w   = (const float*)d_in[10];
    const float* c1_bn  = (const float*)d_in[11];
    const float* c2_w   = (const float*)d_in[12];
    const float* c2_bn  = (const float*)d_in[13];
    const float* fc2_w  = (const float*)d_in[14];
    const float* fc2_bn = (const float*)d_in[15];
    float* out = (float*)d_out;

    cudaFuncSetAttribute(k_front,  cudaFuncAttributeMaxDynamicSharedMemorySize, F_SMEM);
    cudaFuncSetAttribute(k_fc2kv,  cudaFuncAttributeMaxDynamicSharedMemorySize, C_SMEM);

    k_zero<<<8,256>>>();
    k_front<<<dim3(NN/TPX,BB),288,F_SMEM>>>(x,q_w,q_b,k_w,k_b,v_w,v_b,fc1_w,fc1_bn);
    k_dw<<<dim3(WW/32,HH/16,BB*CC),dim3(16,16)>>>(c1_w,c1_bn,c2_w,c2_bn);
    k_fc2kv<<<dim3(NN/TPX,BB),256,C_SMEM>>>(fc2_w,fc2_bn);
    k_out<<<BN/1024,256>>>(x,gamma,out);
}

// round 11
// speedup vs baseline: 1.8720x; 1.0461x over previous
#include <cuda_runtime.h>
#include <cuda_fp16.h>
#include <math.h>
#include <stdint.h>

#define BB 4
#define CC 64
#define MM 8
#define HH 224
#define WW 224
#define NN (HH*WW)      // 50176
#define BN (BB*NN)      // 200704
#define TPX 128         // pixels per CTA tile

// Scratch (static device globals — allocation-free per harness rules)
__device__ __half g_h[BB*CC*NN];
__device__ __half g_s[BB*CC*NN];
__device__ float g_Q[BB*MM*NN];
__device__ float g_K[BB*MM*NN];
__device__ float g_KV[BB*MM*CC];
__device__ float g_Ksum[BB*MM];

__device__ __forceinline__ float relu6f(float x){ return fminf(fmaxf(x,0.f),6.f); }
// fast softplus: max(x,0) + log(1+exp(-|x|)) with MUFU-based intrinsics
__device__ __forceinline__ float softplusf(float x){
    return fmaxf(x,0.f) + __logf(1.f + __expf(-fabsf(x)));
}
__device__ __forceinline__ uint32_t smem_u32(const void* p){
    uint32_t a;
    asm("{ .reg .u64 t; cvta.to.shared.u64 t, %1; cvt.u32.u64 %0, t; }" : "=r"(a) : "l"(p));
    return a;
}
__device__ __forceinline__ void ldsm4(uint32_t* r, uint32_t a){
    asm volatile("ldmatrix.sync.aligned.m8n8.x4.shared.b16 {%0,%1,%2,%3}, [%4];"
        : "=r"(r[0]),"=r"(r[1]),"=r"(r[2]),"=r"(r[3]) : "r"(a));
}
__device__ __forceinline__ void ldsm4t(uint32_t* r, uint32_t a){
    asm volatile("ldmatrix.sync.aligned.m8n8.x4.trans.shared.b16 {%0,%1,%2,%3}, [%4];"
        : "=r"(r[0]),"=r"(r[1]),"=r"(r[2]),"=r"(r[3]) : "r"(a));
}
__device__ __forceinline__ void mma16816h(float* d, const uint32_t* a, const uint32_t* b){
    asm volatile("mma.sync.aligned.m16n8k16.row.col.f32.f16.f16.f32 "
        "{%0,%1,%2,%3}, {%4,%5,%6,%7}, {%8,%9}, {%0,%1,%2,%3};"
        : "+f"(d[0]),"+f"(d[1]),"+f"(d[2]),"+f"(d[3])
        : "r"(a[0]),"r"(a[1]),"r"(a[2]),"r"(a[3]), "r"(b[0]),"r"(b[1]));
}

__global__ void k_zero(){
    int i = blockIdx.x*blockDim.x + threadIdx.x;
    if (i < BB*MM*CC) g_KV[i]   = 0.f;
    if (i < BB*MM)    g_Ksum[i] = 0.f;
}

// ---------------------------------------------------------------------------
// K1 front (fp16 mma.sync): D[144 out, 128 px] = W[144,64] x Xt[64,128]
// outputs: [v(0..63) | fc1(64..127) | q(128..135) | k(136..143)]
// 288 threads = 9 warps. Fused in-block KV-partial = K · (v-conv + bias).
// ---------------------------------------------------------------------------
#define F_WH  0
#define F_XH  20736
#define F_CST 38144
#define F_SMEM 38976
#define F_VS   0
#define F_KF   33280
#define WS 72     // weight smem row stride (f16 elems)
#define XS 136    // x smem row stride (f16 elems)

__global__ __launch_bounds__(288,2) void k_front(
    const float* __restrict__ x,
    const float* __restrict__ q_w, const float* __restrict__ q_b,
    const float* __restrict__ k_w, const float* __restrict__ k_b,
    const float* __restrict__ v_w, const float* __restrict__ v_b,
    const float* __restrict__ fc1_w, const float* __restrict__ fc1_bn)
{
    extern __shared__ char sm[];
    __half* wH = (__half*)(sm + F_WH);
    __half* xH = (__half*)(sm + F_XH);
    float* s_vb   = (float*)(sm + F_CST);         // 64
    float* s_finv = s_vb + 64;                    // 64
    float* s_fbeta= s_finv + 64;                  // 64
    float* s_qb   = s_fbeta + 64;                 // 8
    float* s_kb   = s_qb + 8;                     // 8
    float* v_s    = (float*)(sm + F_VS);          // alias: [128][65]
    float* s_Kf   = (float*)(sm + F_KF);          // alias: [8][128]
    uint32_t sb = smem_u32(sm);

    int tid = threadIdx.x;
    int b  = blockIdx.y;
    int n0 = blockIdx.x * TPX;

    // weights: 144 x 64 -> fp16
    for (int i=tid; i<144*32; i+=288){
        int o = i>>5, c2 = (i&31)<<1;
        const float* src = (o<64) ? v_w + o*64
                         : (o<128)? fc1_w + (o-64)*64
                         : (o<136)? q_w + (o-128)*64
                         :          k_w + (o-136)*64;
        *(half2*)(wH + o*WS + c2) = __floats2half2_rn(src[c2], src[c2+1]);
    }
    // x tile: [64 ch][128 px] -> fp16
    const float* xb = x + (size_t)b*CC*NN + n0;
    for (int i=tid; i<64*64; i+=288){
        int c = i>>6, p2 = (i&63)<<1;
        float2 v = *(const float2*)(xb + (size_t)c*NN + p2);
        *(half2*)(xH + c*XS + p2) = __floats2half2_rn(v.x, v.y);
    }
    if (tid < 64){
        s_vb[tid] = v_b[tid];
        float sc=fc1_bn[0*CC+tid], bi=fc1_bn[1*CC+tid];
        float mn=fc1_bn[2*CC+tid], vr=fc1_bn[3*CC+tid];
        float inv = sc*rsqrtf(vr+1e-5f);
        s_finv[tid]=inv; s_fbeta[tid]=bi-mn*inv;
    } else if (tid < 72){
        s_qb[tid-64] = q_b[tid-64];
        s_kb[tid-64] = k_b[tid-64];
    }
    __syncthreads();

    int w = tid >> 5, lane = tid & 31;
    int m0 = w*16;

    float acc[16][4];
    #pragma unroll
    for (int i=0;i<16;i++){ acc[i][0]=acc[i][1]=acc[i][2]=acc[i][3]=0.f; }

    int arow = m0 + (lane & 15), acol8 = (lane>>4)*8;
    int brow = (lane & 7) + 8*((lane>>3)&1), bcol8 = (lane>>4)*8;

    #pragma unroll
    for (int kt=0; kt<4; kt++){
        int k0 = kt*16;
        uint32_t a[4];
        ldsm4(a, sb + F_WH + (uint32_t)(arow*WS + k0 + acol8)*2);
        #pragma unroll
        for (int np=0; np<8; np++){
            uint32_t bF[4];
            ldsm4t(bF, sb + F_XH + (uint32_t)((k0+brow)*XS + np*16 + bcol8)*2);
            mma16816h(acc[2*np],   a, bF);
            mma16816h(acc[2*np+1], a, bF+2);
        }
    }

    __syncthreads();   // all warps done reading smem operands -> safe to alias

    int g = lane >> 2, t2 = (lane & 3)*2;
    if (w < 4){
        // V partial = conv + bias -> smem only
        int o0 = m0 + g, o1 = o0 + 8;
        float b0 = s_vb[o0], b1 = s_vb[o1];
        #pragma unroll
        for (int nt=0; nt<16; nt++){
            int px = nt*8 + t2;
            v_s[ px   *65 + o0] = acc[nt][0]+b0;
            v_s[(px+1)*65 + o0] = acc[nt][1]+b0;
            v_s[ px   *65 + o1] = acc[nt][2]+b1;
            v_s[(px+1)*65 + o1] = acc[nt][3]+b1;
        }
    } else if (w < 8){
        int o0 = m0 - 64 + g, o1 = o0 + 8;
        float i0=s_finv[o0], e0=s_fbeta[o0], i1=s_finv[o1], e1=s_fbeta[o1];
        __half* p0 = g_h + ((size_t)b*CC + o0)*NN + n0 + t2;
        __half* p1 = g_h + ((size_t)b*CC + o1)*NN + n0 + t2;
        #pragma unroll
        for (int nt=0; nt<16; nt++){
            *(half2*)(p0 + nt*8) = __floats2half2_rn(relu6f(acc[nt][0]*i0+e0), relu6f(acc[nt][1]*i0+e0));
            *(half2*)(p1 + nt*8) = __floats2half2_rn(relu6f(acc[nt][2]*i1+e1), relu6f(acc[nt][3]*i1+e1));
        }
    } else {
        // rows g -> Q[m=g], rows g+8 -> K[m=g]
        float bq = s_qb[g], bk = s_kb[g];
        float* pq = g_Q + ((size_t)b*MM + g)*NN + n0 + t2;
        float* pk = g_K + ((size_t)b*MM + g)*NN + n0 + t2;
        float ksum = 0.f;
        #pragma unroll
        for (int nt=0; nt<16; nt++){
            int px = nt*8 + t2;
            float q0 = softplusf(acc[nt][0]+bq), q1 = softplusf(acc[nt][1]+bq);
            float k0v = softplusf(acc[nt][2]+bk), k1v = softplusf(acc[nt][3]+bk);
            *(float2*)(pq + nt*8) = make_float2(q0, q1);
            *(float2*)(pk + nt*8) = make_float2(k0v, k1v);
            s_Kf[g*TPX + px]   = k0v;
            s_Kf[g*TPX + px+1] = k1v;
            ksum += k0v + k1v;
        }
        ksum += __shfl_xor_sync(0xffffffffu, ksum, 1);
        ksum += __shfl_xor_sync(0xffffffffu, ksum, 2);
        if ((lane & 3) == 0) atomicAdd(&g_Ksum[b*MM + g], ksum);
    }
    __syncthreads();

    // KV-partial reduction (split chains for shorter dependency tails)
    if (tid < 256){
        int m = tid >> 6, c = tid & 63;
        const float* k0r = s_Kf + m*TPX;
        const float* k1r = s_Kf + (m+4)*TPX;
        float a0=0.f, a1=0.f, c0=0.f, c1=0.f;
        #pragma unroll 8
        for (int p=0;p<TPX/2;p++){
            float v = v_s[p*65 + c];
            a0 = fmaf(k0r[p], v, a0);
            a1 = fmaf(k1r[p], v, a1);
        }
        #pragma unroll 8
        for (int p=TPX/2;p<TPX;p++){
            float v = v_s[p*65 + c];
            c0 = fmaf(k0r[p], v, c0);
            c1 = fmaf(k1r[p], v, c1);
        }
        atomicAdd(&g_KV[b*MM*CC + m*CC     + c], a0+c0);
        atomicAdd(&g_KV[b*MM*CC + (m+4)*CC + c], a1+c1);
    }
}

// ---------------------------------------------------------------------------
// K2: depthwise 5x5 + 3x3 (both BN+ReLU6), summed -> g_s (fp16 in/out)
// ---------------------------------------------------------------------------
__global__ __launch_bounds__(256) void k_dw(
    const float* __restrict__ w5, const float* __restrict__ bn5,
    const float* __restrict__ w3, const float* __restrict__ bn3)
{
    int bc = blockIdx.z;
    int c  = bc & (CC-1);
    int y0 = blockIdx.y*16, x0 = blockIdx.x*32;

    __shared__ float t[20][36];
    __shared__ float s_w5[25], s_w3[9], s_c[4];

    int tid = threadIdx.y*16 + threadIdx.x;
    const __half* plane = g_h + (size_t)bc*NN;

    for (int i=tid;i<20*36;i+=256){
        int ly=i/36, lx=i%36;
        int gy=y0+ly-2, gx=x0+lx-2;
        float v = 0.f;
        if (gy>=0 && gy<HH && gx>=0 && gx<WW) v = __half2float(plane[gy*WW+gx]);
        t[ly][lx] = v;
    }
    if (tid<25) s_w5[tid] = w5[c*25+tid];
    if (tid<9)  s_w3[tid] = w3[c*9+tid];
    if (tid==0){
        float inv = bn5[0*CC+c]*rsqrtf(bn5[3*CC+c]+1e-5f);
        s_c[0]=inv; s_c[1]=bn5[1*CC+c]-bn5[2*CC+c]*inv;
    }
    if (tid==32){
        float inv = bn3[0*CC+c]*rsqrtf(bn3[3*CC+c]+1e-5f);
        s_c[2]=inv; s_c[3]=bn3[1*CC+c]-bn3[2*CC+c]*inv;
    }
    __syncthreads();

    int ty = threadIdx.y;        // 0..15 (row)
    int tx2 = threadIdx.x*2;     // 0,2,..,30 (2 px per thread)

    float a5a=0.f, a5b=0.f;
    #pragma unroll
    for (int i=0;i<5;i++){
        const float* r = &t[ty+i][tx2];
        float c0=r[0], c1=r[1], c2=r[2], c3=r[3], c4=r[4], c5=r[5];
        float w0=s_w5[i*5], w1=s_w5[i*5+1], w2=s_w5[i*5+2], w3v=s_w5[i*5+3], w4=s_w5[i*5+4];
        a5a = fmaf(w0,c0, fmaf(w1,c1, fmaf(w2,c2, fmaf(w3v,c3, fmaf(w4,c4, a5a)))));
        a5b = fmaf(w0,c1, fmaf(w1,c2, fmaf(w2,c3, fmaf(w3v,c4, fmaf(w4,c5, a5b)))));
    }
    float a3a=0.f, a3b=0.f;
    #pragma unroll
    for (int i=0;i<3;i++){
        const float* r = &t[ty+1+i][tx2+1];
        float c0=r[0], c1=r[1], c2=r[2], c3=r[3];
        float w0=s_w3[i*3], w1=s_w3[i*3+1], w2=s_w3[i*3+2];
        a3a = fmaf(w0,c0, fmaf(w1,c1, fmaf(w2,c2, a3a)));
        a3b = fmaf(w0,c1, fmaf(w1,c2, fmaf(w2,c3, a3b)));
    }

    float ra = relu6f(a5a*s_c[0]+s_c[1]) + relu6f(a3a*s_c[2]+s_c[3]);
    float rb = relu6f(a5b*s_c[0]+s_c[1]) + relu6f(a3b*s_c[2]+s_c[3]);
    *(half2*)(g_s + (size_t)bc*NN + (y0+ty)*WW + (x0+tx2)) = __floats2half2_rn(ra, rb);
}

// ---------------------------------------------------------------------------
// K3: fc2 (fp16 mma.sync) + fused KV of xc only.
// ---------------------------------------------------------------------------
#define C_AH  0
#define C_XH  9216
#define C_VS  0
#define C_KT  33280
#define C_INV 37376
#define C_BETA 37632
#define C_SMEM 37888

__global__ __launch_bounds__(256,4) void k_fc2kv(
    const float* __restrict__ fc2_w, const float* __restrict__ fc2_bn)
{
    extern __shared__ char sm[];
    __half* aH = (__half*)(sm + C_AH);
    __half* xH = (__half*)(sm + C_XH);
    float* s_K   = (float*)(sm + C_KT);
    float* s_inv = (float*)(sm + C_INV);
    float* s_beta= (float*)(sm + C_BETA);
    float* v_s   = (float*)(sm + C_VS);   // alias, used after mainloop
    uint32_t sb = smem_u32(sm);

    int tid = threadIdx.x;
    int b  = blockIdx.y;
    int n0 = blockIdx.x * TPX;

    // weights 64x64 -> fp16
    for (int i=tid; i<64*32; i+=256){
        int o = i>>5, c2 = (i&31)<<1;
        *(half2*)(aH + o*WS + c2) = __floats2half2_rn(fc2_w[o*64+c2], fc2_w[o*64+c2+1]);
    }
    // s tile [64 ch][128 px] — raw fp16 copy
    const __half* sp = g_s + (size_t)b*CC*NN + n0;
    for (int i=tid; i<64*16; i+=256){
        int c = i>>4, p8 = (i&15)<<3;
        *(uint4*)(xH + c*XS + p8) = *(const uint4*)(sp + (size_t)c*NN + p8);
    }
    // K tile [8][128]
    {
        int m = tid >> 5, p = tid & 31;
        ((float4*)s_K)[m*(TPX/4)+p] =
            ((const float4*)(g_K + ((size_t)b*MM + m)*NN + n0))[p];
    }
    if (tid < 64){
        float sc=fc2_bn[0*CC+tid], bi=fc2_bn[1*CC+tid];
        float mn=fc2_bn[2*CC+tid], vr=fc2_bn[3*CC+tid];
        float inv = sc*rsqrtf(vr+1e-5f);
        s_inv[tid]=inv; s_beta[tid]=bi-mn*inv;
    }
    __syncthreads();

    int w = tid >> 5, lane = tid & 31;
    int mt = w & 3, ph = w >> 2;
    int m0 = mt*16, p0 = ph*64;

    float acc[8][4];
    #pragma unroll
    for (int i=0;i<8;i++){ acc[i][0]=acc[i][1]=acc[i][2]=acc[i][3]=0.f; }

    int arow = m0 + (lane & 15), acol8 = (lane>>4)*8;
    int brow = (lane & 7) + 8*((lane>>3)&1), bcol8 = (lane>>4)*8;

    #pragma unroll
    for (int kt=0; kt<4; kt++){
        int k0 = kt*16;
        uint32_t a[4];
        ldsm4(a, sb + C_AH + (uint32_t)(arow*WS + k0 + acol8)*2);
        #pragma unroll
        for (int np=0; np<4; np++){
            uint32_t bF[4];
            ldsm4t(bF, sb + C_XH + (uint32_t)((k0+brow)*XS + p0 + np*16 + bcol8)*2);
            mma16816h(acc[2*np],   a, bF);
            mma16816h(acc[2*np+1], a, bF+2);
        }
    }

    __syncthreads();   // everyone done reading xH -> reuse as v_s

    // epilogue: xc = relu6(bn(D)) -> smem directly
    int g = lane >> 2, t2 = (lane & 3)*2;
    int o0 = m0 + g, o1 = o0 + 8;
    float i0 = s_inv[o0], e0 = s_beta[o0], i1 = s_inv[o1], e1 = s_beta[o1];
    #pragma unroll
    for (int nt=0; nt<8; nt++){
        int px = p0 + nt*8 + t2;
        v_s[ px   *65 + o0] = relu6f(acc[nt][0]*i0+e0);
        v_s[(px+1)*65 + o0] = relu6f(acc[nt][1]*i0+e0);
        v_s[ px   *65 + o1] = relu6f(acc[nt][2]*i1+e1);
        v_s[(px+1)*65 + o1] = relu6f(acc[nt][3]*i1+e1);
    }
    __syncthreads();

    // KV reduction over xc (split chains)
    {
        int m = tid >> 6, c = tid & 63;
        const float* k0r = s_K + m*TPX;
        const float* k1r = s_K + (m+4)*TPX;
        float a0=0.f, a1=0.f, c0=0.f, c1=0.f;
        #pragma unroll 8
        for (int p=0;p<TPX/2;p++){
            float v = v_s[p*65 + c];
            a0 = fmaf(k0r[p], v, a0);
            a1 = fmaf(k1r[p], v, a1);
        }
        #pragma unroll 8
        for (int p=TPX/2;p<TPX;p++){
            float v = v_s[p*65 + c];
            c0 = fmaf(k0r[p], v, c0);
            c1 = fmaf(k1r[p], v, c1);
        }
        atomicAdd(&g_KV[b*MM*CC + m*CC     + c], a0+c0);
        atomicAdd(&g_KV[b*MM*CC + (m+4)*CC + c], a1+c1);
    }
}

// ---------------------------------------------------------------------------
// K5: out = x + gamma * (Qt . KV) * norm.
// 2 px/thread (float2), 2-way channel split -> 784 CTAs for occupancy.
// ---------------------------------------------------------------------------
__global__ __launch_bounds__(256) void k_out(
    const float* __restrict__ x, const float* __restrict__ gamma,
    float* __restrict__ out)
{
    __shared__ __align__(16) float s_kv[MM*32];
    __shared__ float s_ks[MM];
    int tid = threadIdx.x;
    int p2 = (blockIdx.x*256 + tid)*2;
    int b = p2/NN, n = p2%NN;     // 512 | NN -> b block-uniform
    int co = blockIdx.y*32;

    if (tid < MM*32){
        int m = tid>>5, j = tid&31;
        s_kv[tid] = g_KV[b*MM*CC + m*CC + co + j];
    }
    if (tid<MM) s_ks[tid] = g_Ksum[b*MM+tid] + 1e-6f;
    __syncthreads();

    float2 q[MM];
    #pragma unroll
    for (int m=0;m<MM;m++)
        q[m] = *(const float2*)(g_Q + (size_t)b*MM*NN + (size_t)m*NN + n);

    float dx=0.f, dy=0.f;
    #pragma unroll
    for (int m=0;m<MM;m++){
        float ks = s_ks[m];
        dx = fmaf(q[m].x, ks, dx);
        dy = fmaf(q[m].y, ks, dy);
    }
    float gm = gamma[0];
    float gsx = gm/dx, gsy = gm/dy;

    const float* xb = x + (size_t)b*CC*NN + (size_t)co*NN + n;
    float* ob = out + (size_t)b*CC*NN + (size_t)co*NN + n;

    #pragma unroll 8
    for (int c=0;c<32;c++){
        float ax=0.f, ay=0.f;
        #pragma unroll
        for (int m=0;m<MM;m++){
            float wv = s_kv[m*32 + c];
            ax = fmaf(q[m].x, wv, ax);
            ay = fmaf(q[m].y, wv, ay);
        }
        float2 xv = *(const float2*)(xb + (size_t)c*NN);
        xv.x = fmaf(gsx, ax, xv.x);
        xv.y = fmaf(gsy, ay, xv.y);
        *(float2*)(ob + (size_t)c*NN) = xv;
    }
}

// ---------------------------------------------------------------------------
extern "C" void kernel_launch(void* const* d_in, const int* in_sizes, int n_in,
                              void* d_out, int out_size)
{
    const float* x      = (const float*)d_in[0];
    const float* gamma  = (const float*)d_in[1];
    const float* q_w    = (const float*)d_in[2];
    const float* q_b    = (const float*)d_in[3];
    const float* k_w    = (const float*)d_in[4];
    const float* k_b    = (const float*)d_in[5];
    const float* v_w    = (const float*)d_in[6];
    const float* v_b    = (const float*)d_in[7];
    const float* fc1_w  = (const float*)d_in[8];
    const float* fc1_bn = (const float*)d_in[9];
    const float* c1_w   = (const float*)d_in[10];
    const float* c1_bn  = (const float*)d_in[11];
    const float* c2_w   = (const float*)d_in[12];
    const float* c2_bn  = (const float*)d_in[13];
    const float* fc2_w  = (const float*)d_in[14];
    const float* fc2_bn = (const float*)d_in[15];
    float* out = (float*)d_out;

    cudaFuncSetAttribute(k_front,  cudaFuncAttributeMaxDynamicSharedMemorySize, F_SMEM);
    cudaFuncSetAttribute(k_fc2kv,  cudaFuncAttributeMaxDynamicSharedMemorySize, C_SMEM);

    k_zero<<<8,256>>>();
    k_front<<<dim3(NN/TPX,BB),288,F_SMEM>>>(x,q_w,q_b,k_w,k_b,v_w,v_b,fc1_w,fc1_bn);
    k_dw<<<dim3(WW/32,HH/16,BB*CC),dim3(16,16)>>>(c1_w,c1_bn,c2_w,c2_bn);
    k_fc2kv<<<dim3(NN/TPX,BB),256,C_SMEM>>>(fc2_w,fc2_bn);
    k_out<<<dim3(BN/512,2),256>>>(x,gamma,out);
}